// round 2
// baseline (speedup 1.0000x reference)
#include <cuda_runtime.h>

#define FPN_C 256
#define SH_C  512
#define NLEV  5
#define BATCHN 2
#define A_TOTAL 261888   // 3 * (65536+16384+4096+1024+256)

// Scratch for shared-conv activations: sum over levels of B*HW*512 floats
// = 89,391,104 floats (~341 MiB). Static __device__ global (allowed).
__device__ float g_scratch[89391104];

// ---------------------------------------------------------------------------
// Stage 1: 3x3 conv 256->512, SAME padding, + bias + ReLU.
// Implicit GEMM: out[HW,512] = sum_{tap} shifted_in[HW,256] x W_tap[256,512].
// Block tile: M=64 pixels, N=64 cout, K-chunk=16. 256 threads, 4x4 microtile.
// ---------------------------------------------------------------------------
__global__ __launch_bounds__(256) void conv3x3_kernel(
    const float* __restrict__ feat,   // [B,H,W,256]
    const float* __restrict__ w,      // [3,3,256,512] HWIO
    const float* __restrict__ bias,   // [512]
    size_t soff,                      // level offset into g_scratch (floats)
    int H, int logW)
{
    __shared__ float As[16][68];   // [k][m], padded
    __shared__ float Bs[16][64];   // [k][n]

    const int tid = threadIdx.x;
    const int tx = tid & 15;       // N direction (4 cols each)
    const int ty = tid >> 4;       // M direction (4 rows each)
    const int W  = H;
    const int HW = H << logW;
    const int m0 = blockIdx.x * 64;
    const int n0 = blockIdx.y * 64;
    const int b  = blockIdx.z;

    const float* fb = feat + (size_t)b * HW * FPN_C;

    // A-tile load mapping: thread -> (pixel, cin4)
    const int am    = m0 + (tid >> 2);
    const int ak4   = (tid & 3) << 2;
    const int asm_m = tid >> 2;
    const int ay = am >> logW;
    const int ax = am & (W - 1);

    // B-tile load mapping: thread -> (k, n4)
    const int bk = tid >> 4;          // 0..15
    const int bn = (tid & 15) << 2;   // 0..60

    float acc[4][4];
    #pragma unroll
    for (int i = 0; i < 4; i++)
        #pragma unroll
        for (int j = 0; j < 4; j++) acc[i][j] = 0.0f;

    #pragma unroll 1
    for (int tap = 0; tap < 9; ++tap) {
        const int iy = ay + tap / 3 - 1;
        const int ix = ax + tap % 3 - 1;
        const bool inb = ((unsigned)iy < (unsigned)H) && ((unsigned)ix < (unsigned)W);
        const float* arow = fb + (((size_t)iy << logW) + ix) * FPN_C + ak4;
        const float* wt   = w + (size_t)tap * FPN_C * SH_C + (size_t)bk * SH_C + n0 + bn;

        #pragma unroll 1
        for (int kb = 0; kb < FPN_C; kb += 16) {
            float4 av = inb ? *(const float4*)(arow + kb)
                            : make_float4(0.f, 0.f, 0.f, 0.f);
            float4 bv = *(const float4*)(wt + (size_t)kb * SH_C);

            __syncthreads();   // previous chunk's compute done
            As[ak4 + 0][asm_m] = av.x;
            As[ak4 + 1][asm_m] = av.y;
            As[ak4 + 2][asm_m] = av.z;
            As[ak4 + 3][asm_m] = av.w;
            *(float4*)&Bs[bk][bn] = bv;
            __syncthreads();   // tiles visible

            #pragma unroll
            for (int k = 0; k < 16; k++) {
                float4 a  = *(const float4*)&As[k][ty << 2];
                float4 bb = *(const float4*)&Bs[k][tx << 2];
                float ar[4] = {a.x, a.y, a.z, a.w};
                float br[4] = {bb.x, bb.y, bb.z, bb.w};
                #pragma unroll
                for (int i = 0; i < 4; i++)
                    #pragma unroll
                    for (int j = 0; j < 4; j++)
                        acc[i][j] += ar[i] * br[j];
            }
        }
    }

    // Epilogue: bias + ReLU -> scratch [b, pixel, cout]
    float4 bb = *(const float4*)(bias + n0 + (tx << 2));
    float* obase = g_scratch + soff + (size_t)b * HW * SH_C + n0 + (tx << 2);
    #pragma unroll
    for (int i = 0; i < 4; i++) {
        int m = m0 + (ty << 2) + i;
        float4 v;
        v.x = fmaxf(acc[i][0] + bb.x, 0.f);
        v.y = fmaxf(acc[i][1] + bb.y, 0.f);
        v.z = fmaxf(acc[i][2] + bb.z, 0.f);
        v.w = fmaxf(acc[i][3] + bb.w, 0.f);
        *(float4*)(obase + (size_t)m * SH_C) = v;
    }
}

// ---------------------------------------------------------------------------
// Stage 2: fused 1x1 heads (cls:6, delta:12) + softmax + scatter into the
// concatenated output (logits | probs | deltas).
// 128 threads/block, one pixel per thread; 18 weight columns in smem.
// ---------------------------------------------------------------------------
__global__ __launch_bounds__(128) void head_kernel(
    size_t soff,
    const float* __restrict__ w_cls,    // [512,6]
    const float* __restrict__ b_cls,    // [6]
    const float* __restrict__ w_delta,  // [512,12]
    const float* __restrict__ b_delta,  // [12]
    float* __restrict__ out,
    int HW, int aoff)
{
    __shared__ float ws[SH_C * 18];
    __shared__ float bs[18];

    const int tid = threadIdx.x;
    for (int i = tid; i < SH_C * 6; i += 128) {
        int c = i / 6, j = i % 6;
        ws[c * 18 + j] = w_cls[i];
    }
    for (int i = tid; i < SH_C * 12; i += 128) {
        int c = i / 12, j = i % 12;
        ws[c * 18 + 6 + j] = w_delta[i];
    }
    if (tid < 6)       bs[tid] = b_cls[tid];
    else if (tid < 18) bs[tid] = b_delta[tid - 6];
    __syncthreads();

    const int m = blockIdx.x * 128 + tid;
    const int b = blockIdx.z;
    const float* row = g_scratch + soff + ((size_t)b * HW + m) * SH_C;

    float acc[18];
    #pragma unroll
    for (int j = 0; j < 18; j++) acc[j] = bs[j];

    #pragma unroll 4
    for (int c = 0; c < SH_C; c += 4) {
        float4 s = *(const float4*)(row + c);
        float sv[4] = {s.x, s.y, s.z, s.w};
        #pragma unroll
        for (int e = 0; e < 4; e++) {
            const float* wrow = &ws[(c + e) * 18];
            #pragma unroll
            for (int j = 0; j < 18; j++) acc[j] += sv[e] * wrow[j];
        }
    }

    float* out_logits = out;
    float* out_probs  = out + (size_t)BATCHN * A_TOTAL * 2;
    float* out_deltas = out + (size_t)2 * BATCHN * A_TOTAL * 2;

    #pragma unroll
    for (int r = 0; r < 3; r++) {
        float l0 = acc[2 * r], l1 = acc[2 * r + 1];
        size_t a = (size_t)b * A_TOTAL + (size_t)aoff + (size_t)m * 3 + r;
        out_logits[a * 2 + 0] = l0;
        out_logits[a * 2 + 1] = l1;
        float mx = fmaxf(l0, l1);
        float e0 = __expf(l0 - mx), e1 = __expf(l1 - mx);
        float inv = 1.0f / (e0 + e1);
        out_probs[a * 2 + 0] = e0 * inv;
        out_probs[a * 2 + 1] = e1 * inv;
        #pragma unroll
        for (int k = 0; k < 4; k++)
            out_deltas[a * 4 + k] = acc[6 + 4 * r + k];
    }
}

// ---------------------------------------------------------------------------
extern "C" void kernel_launch(void* const* d_in, const int* in_sizes, int n_in,
                              void* d_out, int out_size)
{
    const float* feats[NLEV];
    for (int i = 0; i < NLEV; i++) feats[i] = (const float*)d_in[i];
    const float* w_shared = (const float*)d_in[5];
    const float* b_shared = (const float*)d_in[6];
    const float* w_cls    = (const float*)d_in[7];
    const float* b_cls    = (const float*)d_in[8];
    const float* w_delta  = (const float*)d_in[9];
    const float* b_delta  = (const float*)d_in[10];
    float* out = (float*)d_out;

    static const int    hs[NLEV]   = {256, 128, 64, 32, 16};
    static const int    logw[NLEV] = {8, 7, 6, 5, 4};
    static const size_t soff[NLEV] = {0, 67108864, 83886080, 88080384, 89128960};
    static const int    aoff[NLEV] = {0, 196608, 245760, 258048, 261120};

    for (int l = 0; l < NLEV; l++) {
        int H = hs[l], HW = H * H;
        dim3 g1(HW / 64, SH_C / 64, BATCHN);
        conv3x3_kernel<<<g1, 256>>>(feats[l], w_shared, b_shared,
                                    soff[l], H, logw[l]);
    }
    for (int l = 0; l < NLEV; l++) {
        int H = hs[l], HW = H * H;
        dim3 g2(HW / 128, 1, BATCHN);
        head_kernel<<<g2, 128>>>(soff[l], w_cls, b_cls, w_delta, b_delta,
                                 out, HW, aoff[l]);
    }
}

// round 4
// speedup vs baseline: 5.1197x; 5.1197x over previous
#include <cuda_runtime.h>
#include <cuda_bf16.h>
#include <cstdint>

#define FPN_C 256
#define SH_C  512
#define NLEV  5
#define BATCHN 2
#define A_TOTAL 261888

// ---------------- scratch layout (bytes) ----------------
#define OUT_OFF 0
#define FHI_OFF 357564416ULL
#define FLO_OFF 446955520ULL
#define WHI_OFF 536346624ULL
#define WLO_OFF 538705920ULL
__device__ __align__(4096) unsigned char g_scratch[541065216];

// ---------------- PTX helpers ----------------
__device__ __forceinline__ uint32_t smem_u32(const void* p) {
    uint32_t a;
    asm("{ .reg .u64 t; cvta.to.shared.u64 t, %1; cvt.u32.u64 %0, t; }" : "=r"(a) : "l"(p));
    return a;
}
__device__ __forceinline__ void cp16(uint32_t sa, const void* g, uint32_t srcsz) {
    asm volatile("cp.async.cg.shared.global [%0], [%1], 16, %2;" :: "r"(sa), "l"(g), "r"(srcsz));
}
#define CP_COMMIT() asm volatile("cp.async.commit_group;" ::: "memory")
#define CP_WAIT2()  asm volatile("cp.async.wait_group 2;" ::: "memory")
#define CP_WAIT0()  asm volatile("cp.async.wait_group 0;" ::: "memory")

__device__ __forceinline__ void ldsm4(uint32_t* r, uint32_t a) {
    asm volatile("ldmatrix.sync.aligned.m8n8.x4.shared.b16 {%0,%1,%2,%3}, [%4];"
        : "=r"(r[0]), "=r"(r[1]), "=r"(r[2]), "=r"(r[3]) : "r"(a));
}
__device__ __forceinline__ void ldsm2(uint32_t* r, uint32_t a) {
    asm volatile("ldmatrix.sync.aligned.m8n8.x2.shared.b16 {%0,%1}, [%2];"
        : "=r"(r[0]), "=r"(r[1]) : "r"(a));
}
__device__ __forceinline__ void mma16816(float* d, const uint32_t* a, const uint32_t* b) {
    asm volatile("mma.sync.aligned.m16n8k16.row.col.f32.bf16.bf16.f32 "
        "{%0,%1,%2,%3}, {%4,%5,%6,%7}, {%8,%9}, {%0,%1,%2,%3};"
        : "+f"(d[0]), "+f"(d[1]), "+f"(d[2]), "+f"(d[3])
        : "r"(a[0]), "r"(a[1]), "r"(a[2]), "r"(a[3]), "r"(b[0]), "r"(b[1]));
}
__device__ __forceinline__ uint32_t sw128(uint32_t off) {
    return off ^ ((off >> 3) & 0x70);
}

// stage: A_hi[0,16K) A_lo[16K,32K) B_hi[32K,48K) B_lo[48K,64K)
#define STAGE_BYTES 65536
#define NSTAGE 3
#define SMEM_TOTAL (NSTAGE * STAGE_BYTES)

// ---------------------------------------------------------------------------
// prep: fp32 -> (hi, lo) bf16 splits
// ---------------------------------------------------------------------------
__global__ void split_feat(const float* __restrict__ src, size_t eoff, int n) {
    __nv_bfloat16* hi = (__nv_bfloat16*)(g_scratch + FHI_OFF) + eoff;
    __nv_bfloat16* lo = (__nv_bfloat16*)(g_scratch + FLO_OFF) + eoff;
    for (int i = blockIdx.x * blockDim.x + threadIdx.x; i < n; i += gridDim.x * blockDim.x) {
        float x = src[i];
        __nv_bfloat16 h = __float2bfloat16(x);
        hi[i] = h;
        lo[i] = __float2bfloat16(x - __bfloat162float(h));
    }
}
// weights [tap][cin][cout] -> [tap][cout][cin] hi/lo
__global__ void split_w(const float* __restrict__ w) {
    __nv_bfloat16* hi = (__nv_bfloat16*)(g_scratch + WHI_OFF);
    __nv_bfloat16* lo = (__nv_bfloat16*)(g_scratch + WLO_OFF);
    int n = 9 * FPN_C * SH_C;
    for (int i = blockIdx.x * blockDim.x + threadIdx.x; i < n; i += gridDim.x * blockDim.x) {
        int tap = i / (FPN_C * SH_C);
        int rem = i - tap * FPN_C * SH_C;
        int cin = rem / SH_C, cout = rem - cin * SH_C;
        float x = w[i];
        __nv_bfloat16 h = __float2bfloat16(x);
        size_t o = ((size_t)tap * SH_C + cout) * FPN_C + cin;
        hi[o] = h;
        lo[o] = __float2bfloat16(x - __bfloat162float(h));
    }
}

// ---------------------------------------------------------------------------
// Stage 1: 3x3 conv 256->512 + bias + ReLU, split-bf16 HMMA implicit GEMM.
// CTA: M=128 pixels x N=128 couts. K = 9 taps x 256 cin, kchunk=64.
// 8 warps: warp grid 2(M) x 4(N), warp tile 64x32.
// ---------------------------------------------------------------------------
__global__ __launch_bounds__(256, 1) void conv3_mma(
    size_t f_eoff, size_t soff, const float* __restrict__ bias, int H, int logW)
{
    extern __shared__ __align__(1024) char smem[];
    const uint32_t sbase = smem_u32(smem);
    const int tid = threadIdx.x;
    const int wid = tid >> 5, lid = tid & 31;
    const int warp_m = wid >> 2;        // 0..1
    const int warp_n = wid & 3;         // 0..3

    const int W = H, HW = H << logW;
    const int m0 = blockIdx.x * 128;
    const int n0 = blockIdx.y * 128;
    const int b = blockIdx.z;
    const int bHW = b * HW;

    const __nv_bfloat16* fhi = (const __nv_bfloat16*)(g_scratch + FHI_OFF) + f_eoff;
    const __nv_bfloat16* flo = (const __nv_bfloat16*)(g_scratch + FLO_OFF) + f_eoff;
    const __nv_bfloat16* whi = (const __nv_bfloat16*)(g_scratch + WHI_OFF);
    const __nv_bfloat16* wlo = (const __nv_bfloat16*)(g_scratch + WLO_OFF);

    float acc[4][4][4];
    #pragma unroll
    for (int i = 0; i < 4; i++)
        #pragma unroll
        for (int j = 0; j < 4; j++)
            #pragma unroll
            for (int k = 0; k < 4; k++) acc[i][j][k] = 0.0f;

    // ---- async loader for iteration it = tap*4 + kc ----
    auto load_stage = [&](int it) {
        const int tap = it >> 2, kc = it & 3;
        const int dy = tap / 3 - 1, dx = tap % 3 - 1;
        const uint32_t stg = sbase + (it % NSTAGE) * STAGE_BYTES;
        // A: 2048 x 16B (hi then lo): [part][r=128][col8=8]
        #pragma unroll
        for (int j = 0; j < 8; j++) {
            int c = tid + 256 * j;
            int part = c >> 10, r = (c >> 3) & 127, col8 = c & 7;
            int m = m0 + r;
            int y = m >> logW, x = m & (W - 1);
            int iy = y + dy, ix = x + dx;
            bool inb = ((unsigned)iy < (unsigned)H) && ((unsigned)ix < (unsigned)W);
            int pix = inb ? ((iy << logW) + ix) : 0;
            const __nv_bfloat16* src = (part ? flo : fhi) +
                (((size_t)(bHW + pix)) << 8) + (kc << 6) + (col8 << 3);
            cp16(stg + part * 16384 + sw128(r * 128 + col8 * 16), src, inb ? 16u : 0u);
        }
        // B: 2048 x 16B (hi then lo): rows n0..n0+127
        #pragma unroll
        for (int j = 0; j < 8; j++) {
            int c = tid + 256 * j;
            int part = c >> 10, r = (c >> 3) & 127, col8 = c & 7;
            const __nv_bfloat16* src = (part ? wlo : whi) +
                (((size_t)(tap * SH_C + n0 + r)) << 8) + (kc << 6) + (col8 << 3);
            cp16(stg + 32768 + part * 16384 + sw128(r * 128 + col8 * 16), src, 16u);
        }
    };

    load_stage(0); CP_COMMIT();
    load_stage(1); CP_COMMIT();

    for (int it = 0; it < 36; ++it) {
        if (it + 2 < 36) load_stage(it + 2);
        CP_COMMIT();          // empty groups near the tail keep the count uniform
        CP_WAIT2();           // stage `it` complete
        __syncthreads();

        const uint32_t stg = sbase + (it % NSTAGE) * STAGE_BYTES;
        #pragma unroll
        for (int ks = 0; ks < 4; ks++) {
            uint32_t ah[4][4], al[4][4];
            #pragma unroll
            for (int mi = 0; mi < 4; mi++) {
                int m = warp_m * 64 + mi * 16 + (lid & 15);
                int kb = ks * 2 + (lid >> 4);
                uint32_t sw = sw128((uint32_t)(m * 128 + kb * 16));
                ldsm4(ah[mi], stg + sw);
                ldsm4(al[mi], stg + 16384 + sw);
            }
            uint32_t bh[4][2], bl[4][2];
            #pragma unroll
            for (int ni = 0; ni < 4; ni++) {
                int n = warp_n * 32 + ni * 8 + (lid & 7);
                int kb = ks * 2 + ((lid >> 3) & 1);
                uint32_t sw = sw128((uint32_t)(n * 128 + kb * 16));
                ldsm2(bh[ni], stg + 32768 + sw);
                ldsm2(bl[ni], stg + 49152 + sw);
            }
            #pragma unroll
            for (int mi = 0; mi < 4; mi++)
                #pragma unroll
                for (int ni = 0; ni < 4; ni++) {
                    mma16816(acc[mi][ni], ah[mi], bh[ni]);
                    mma16816(acc[mi][ni], ah[mi], bl[ni]);
                    mma16816(acc[mi][ni], al[mi], bh[ni]);
                }
        }
        __syncthreads();      // all warps done with this buffer before reuse
    }
    CP_WAIT0();

    // ---- epilogue: bias + ReLU -> scratch fp32 [b][pixel][512] ----
    float* outp = (float*)(g_scratch + OUT_OFF) + soff;
    const int mb = m0 + warp_m * 64;
    const int nb = n0 + warp_n * 32;
    const int r = lid >> 2, c2 = (lid & 3) * 2;
    #pragma unroll
    for (int ni = 0; ni < 4; ni++) {
        float2 bv = *(const float2*)(bias + nb + ni * 8 + c2);
        #pragma unroll
        for (int mi = 0; mi < 4; mi++) {
            float* p0 = outp + (size_t)(bHW + mb + mi * 16 + r) * SH_C + nb + ni * 8 + c2;
            float* p1 = p0 + 8 * SH_C;
            float2 v0, v1;
            v0.x = fmaxf(acc[mi][ni][0] + bv.x, 0.f);
            v0.y = fmaxf(acc[mi][ni][1] + bv.y, 0.f);
            v1.x = fmaxf(acc[mi][ni][2] + bv.x, 0.f);
            v1.y = fmaxf(acc[mi][ni][3] + bv.y, 0.f);
            *(float2*)p0 = v0;
            *(float2*)p1 = v1;
        }
    }
}

// ---------------------------------------------------------------------------
// Stage 2: fused 1x1 heads + softmax + scatter
// ---------------------------------------------------------------------------
__global__ __launch_bounds__(128) void head_kernel(
    size_t soff,
    const float* __restrict__ w_cls, const float* __restrict__ b_cls,
    const float* __restrict__ w_delta, const float* __restrict__ b_delta,
    float* __restrict__ out, int HW, int aoff)
{
    __shared__ float ws[SH_C * 18];
    __shared__ float bs[18];
    const int tid = threadIdx.x;
    for (int i = tid; i < SH_C * 6; i += 128) {
        int c = i / 6, j = i % 6;
        ws[c * 18 + j] = w_cls[i];
    }
    for (int i = tid; i < SH_C * 12; i += 128) {
        int c = i / 12, j = i % 12;
        ws[c * 18 + 6 + j] = w_delta[i];
    }
    if (tid < 6)       bs[tid] = b_cls[tid];
    else if (tid < 18) bs[tid] = b_delta[tid - 6];
    __syncthreads();

    const int m = blockIdx.x * 128 + tid;
    const int b = blockIdx.z;
    const float* row = (const float*)(g_scratch + OUT_OFF) + soff + ((size_t)b * HW + m) * SH_C;

    float acc[18];
    #pragma unroll
    for (int j = 0; j < 18; j++) acc[j] = bs[j];

    #pragma unroll 4
    for (int c = 0; c < SH_C; c += 4) {
        float4 s = *(const float4*)(row + c);
        float sv[4] = {s.x, s.y, s.z, s.w};
        #pragma unroll
        for (int e = 0; e < 4; e++) {
            const float* wrow = &ws[(c + e) * 18];
            #pragma unroll
            for (int j = 0; j < 18; j++) acc[j] += sv[e] * wrow[j];
        }
    }

    float* out_logits = out;
    float* out_probs  = out + (size_t)BATCHN * A_TOTAL * 2;
    float* out_deltas = out + (size_t)2 * BATCHN * A_TOTAL * 2;

    #pragma unroll
    for (int rr = 0; rr < 3; rr++) {
        float l0 = acc[2 * rr], l1 = acc[2 * rr + 1];
        size_t a = (size_t)b * A_TOTAL + (size_t)aoff + (size_t)m * 3 + rr;
        out_logits[a * 2 + 0] = l0;
        out_logits[a * 2 + 1] = l1;
        float mx = fmaxf(l0, l1);
        float e0 = __expf(l0 - mx), e1 = __expf(l1 - mx);
        float inv = 1.0f / (e0 + e1);
        out_probs[a * 2 + 0] = e0 * inv;
        out_probs[a * 2 + 1] = e1 * inv;
        #pragma unroll
        for (int k = 0; k < 4; k++)
            out_deltas[a * 4 + k] = acc[6 + 4 * rr + k];
    }
}

// ---------------------------------------------------------------------------
extern "C" void kernel_launch(void* const* d_in, const int* in_sizes, int n_in,
                              void* d_out, int out_size)
{
    const float* feats[NLEV];
    for (int i = 0; i < NLEV; i++) feats[i] = (const float*)d_in[i];
    const float* w_shared = (const float*)d_in[5];
    const float* b_shared = (const float*)d_in[6];
    const float* w_cls    = (const float*)d_in[7];
    const float* b_cls    = (const float*)d_in[8];
    const float* w_delta  = (const float*)d_in[9];
    const float* b_delta  = (const float*)d_in[10];
    float* out = (float*)d_out;

    static const int    hs[NLEV]    = {256, 128, 64, 32, 16};
    static const int    logw[NLEV]  = {8, 7, 6, 5, 4};
    static const size_t soff[NLEV]  = {0, 67108864, 83886080, 88080384, 89128960};
    static const size_t feoff[NLEV] = {0, 33554432, 41943040, 44040192, 44564480};
    static const int    aoff[NLEV]  = {0, 196608, 245760, 258048, 261120};

    static bool attr_set = false;
    if (!attr_set) {
        cudaFuncSetAttribute(conv3_mma, cudaFuncAttributeMaxDynamicSharedMemorySize, SMEM_TOTAL);
        attr_set = true;
    }

    split_w<<<1152, 256>>>(w_shared);
    for (int l = 0; l < NLEV; l++) {
        int n = BATCHN * hs[l] * hs[l] * FPN_C;
        int g = (n + 255) / 256; if (g > 8192) g = 8192;
        split_feat<<<g, 256>>>(feats[l], feoff[l], n);
    }
    for (int l = 0; l < NLEV; l++) {
        int HW = hs[l] * hs[l];
        dim3 g(HW / 128, SH_C / 128, BATCHN);
        conv3_mma<<<g, 256, SMEM_TOTAL>>>(feoff[l], soff[l], b_shared, hs[l], logw[l]);
    }
    for (int l = 0; l < NLEV; l++) {
        int HW = hs[l] * hs[l];
        dim3 g(HW / 128, 1, BATCHN);
        head_kernel<<<g, 128>>>(soff[l], w_cls, b_cls, w_delta, b_delta, out, HW, aoff[l]);
    }
}

// round 6
// speedup vs baseline: 6.8340x; 1.3348x over previous
#include <cuda_runtime.h>
#include <cuda_fp16.h>
#include <cstdint>

#define FPN_C 256
#define SH_C  512
#define NLEV  5
#define BATCHN 2
#define A_TOTAL 261888

// ---------------- scratch layout (bytes) ----------------
// conv activations fp32 : [0, 357,564,416)
// feat fp16 (single)    : [FH,  +89,391,104)
// weightT hi fp16       : [WHI, +2,359,296)   [tap][cout=512][cin=256]
// weightT lo fp16       : [WLO, +2,359,296)
#define OUT_OFF 0
#define FH_OFF  357564416ULL
#define WHI_OFF 446955520ULL
#define WLO_OFF 449314816ULL
__device__ __align__(4096) unsigned char g_scratch[451674112];

// ---------------- PTX helpers ----------------
__device__ __forceinline__ uint32_t smem_u32(const void* p) {
    uint32_t a;
    asm("{ .reg .u64 t; cvta.to.shared.u64 t, %1; cvt.u32.u64 %0, t; }" : "=r"(a) : "l"(p));
    return a;
}
__device__ __forceinline__ void cp16(uint32_t sa, const void* g, uint32_t srcsz) {
    asm volatile("cp.async.cg.shared.global [%0], [%1], 16, %2;" :: "r"(sa), "l"(g), "r"(srcsz));
}
#define CP_COMMIT() asm volatile("cp.async.commit_group;" ::: "memory")
#define CP_WAIT1()  asm volatile("cp.async.wait_group 1;" ::: "memory")
#define CP_WAIT0()  asm volatile("cp.async.wait_group 0;" ::: "memory")

__device__ __forceinline__ void ldsm4(uint32_t* r, uint32_t a) {
    asm volatile("ldmatrix.sync.aligned.m8n8.x4.shared.b16 {%0,%1,%2,%3}, [%4];"
        : "=r"(r[0]), "=r"(r[1]), "=r"(r[2]), "=r"(r[3]) : "r"(a));
}
__device__ __forceinline__ void mma_f16(float* d, const uint32_t* a, const uint32_t* b) {
    asm volatile("mma.sync.aligned.m16n8k16.row.col.f32.f16.f16.f32 "
        "{%0,%1,%2,%3}, {%4,%5,%6,%7}, {%8,%9}, {%0,%1,%2,%3};"
        : "+f"(d[0]), "+f"(d[1]), "+f"(d[2]), "+f"(d[3])
        : "r"(a[0]), "r"(a[1]), "r"(a[2]), "r"(a[3]), "r"(b[0]), "r"(b[1]));
}
__device__ __forceinline__ uint32_t sw128(uint32_t off) {
    return off ^ ((off >> 3) & 0x70);
}

// stage: A[0,16K) B_hi[16K,48K) B_lo[48K,80K)
#define STAGE_BYTES 81920
#define SMEM_TOTAL  (2 * STAGE_BYTES)

// ---------------------------------------------------------------------------
// Fused prep: feats fp32 -> fp16 (rn), weights -> transposed fp16 hi/lo split.
// ---------------------------------------------------------------------------
#define F_TOTAL 44695552
#define W_TOTAL 1179648
__global__ __launch_bounds__(256) void split_all(
    const float* __restrict__ f0, const float* __restrict__ f1,
    const float* __restrict__ f2, const float* __restrict__ f3,
    const float* __restrict__ f4, const float* __restrict__ w)
{
    int i = blockIdx.x * 256 + threadIdx.x;
    if (i < F_TOTAL) {
        const float* src;
        int off;
        if (i < 33554432)      { src = f0; off = 0; }
        else if (i < 41943040) { src = f1; off = 33554432; }
        else if (i < 44040192) { src = f2; off = 41943040; }
        else if (i < 44564480) { src = f3; off = 44040192; }
        else                   { src = f4; off = 44564480; }
        ((__half*)(g_scratch + FH_OFF))[i] = __float2half_rn(src[i - off]);
    } else if (i < F_TOTAL + W_TOTAL) {
        int j = i - F_TOTAL;
        int tap = j >> 17;               // / (256*512)
        int rem = j & 131071;
        int cin = rem >> 9, cout = rem & 511;
        float x = w[j];
        __half h = __float2half_rn(x);
        size_t o = ((size_t)(tap * SH_C + cout) << 8) + cin;
        ((__half*)(g_scratch + WHI_OFF))[o] = h;
        ((__half*)(g_scratch + WLO_OFF))[o] = __float2half_rn(x - __half2float(h));
    }
}

// ---------------------------------------------------------------------------
// Stage 1: 3x3 conv 256->512 + bias + ReLU.
// 2-pass fp16 HMMA implicit GEMM: a*w_hi + a*w_lo (weights exact).
// CTA: M=128 pixels x N=256 couts; K = 9 taps x 256 cin, kchunk=64.
// 8 warps as 2(M) x 4(N); warp tile 64x64.
// ---------------------------------------------------------------------------
__global__ __launch_bounds__(256, 1) void conv3_mma(
    size_t f_eoff, size_t soff, const float* __restrict__ bias, int H, int logW)
{
    extern __shared__ __align__(1024) char smem[];
    const uint32_t sbase = smem_u32(smem);
    const int tid = threadIdx.x;
    const int wid = tid >> 5, lid = tid & 31;
    const int warp_m = wid >> 2;        // 0..1
    const int warp_n = wid & 3;         // 0..3

    const int W = H, HW = H << logW;
    const int m0 = blockIdx.x * 128;
    const int n0 = blockIdx.y * 256;
    const int b = blockIdx.z;
    const int bHW = b * HW;

    const __half* fh  = (const __half*)(g_scratch + FH_OFF) + f_eoff;
    const __half* whi = (const __half*)(g_scratch + WHI_OFF);
    const __half* wlo = (const __half*)(g_scratch + WLO_OFF);

    float acc[4][8][4];
    #pragma unroll
    for (int i = 0; i < 4; i++)
        #pragma unroll
        for (int j = 0; j < 8; j++)
            #pragma unroll
            for (int k = 0; k < 4; k++) acc[i][j][k] = 0.0f;

    // ---- async loader for iteration it = tap*4 + kc ----
    auto load_stage = [&](int it) {
        const int tap = it >> 2, kc = it & 3;
        const int dy = tap / 3 - 1, dx = tap % 3 - 1;
        const uint32_t stg = sbase + (it & 1) * STAGE_BYTES;
        // A: 128 rows x 8 chunks of 16B
        #pragma unroll
        for (int j = 0; j < 4; j++) {
            int c = tid + 256 * j;
            int r = c >> 3, col8 = c & 7;
            int m = m0 + r;
            int y = m >> logW, x = m & (W - 1);
            int iy = y + dy, ix = x + dx;
            bool inb = ((unsigned)iy < (unsigned)H) && ((unsigned)ix < (unsigned)W);
            int pix = inb ? ((iy << logW) + ix) : 0;
            const __half* src = fh + (((size_t)(bHW + pix)) << 8) + (kc << 6) + (col8 << 3);
            cp16(stg + sw128(r * 128 + col8 * 16), src, inb ? 16u : 0u);
        }
        // B hi+lo: 256 rows x 8 chunks each
        #pragma unroll
        for (int j = 0; j < 16; j++) {
            int c = tid + 256 * j;
            int part = c >> 11;            // 0=hi, 1=lo
            int r = (c >> 3) & 255, col8 = c & 7;
            const __half* src = (part ? wlo : whi) +
                (((size_t)(tap * SH_C + n0 + r)) << 8) + (kc << 6) + (col8 << 3);
            cp16(stg + 16384 + part * 32768 + sw128(r * 128 + col8 * 16), src, 16u);
        }
    };

    load_stage(0); CP_COMMIT();

    for (int it = 0; it < 36; ++it) {
        if (it + 1 < 36) load_stage(it + 1);
        CP_COMMIT();          // uniform group count (empty at tail)
        CP_WAIT1();           // stage `it` complete
        __syncthreads();

        const uint32_t stg = sbase + (it & 1) * STAGE_BYTES;
        #pragma unroll
        for (int ks = 0; ks < 4; ks++) {
            uint32_t a[4][4];
            #pragma unroll
            for (int mi = 0; mi < 4; mi++) {
                int m = warp_m * 64 + mi * 16 + (lid & 15);
                int kb = ks * 2 + (lid >> 4);
                ldsm4(a[mi], stg + sw128((uint32_t)(m * 128 + kb * 16)));
            }
            #pragma unroll
            for (int nj = 0; nj < 4; nj++) {
                // pair of 8-wide n-groups: lanes 0-15 -> ni=2nj, 16-31 -> 2nj+1
                int n = warp_n * 64 + nj * 16 + (lid & 7) + ((lid >> 4) << 3);
                int kb = ks * 2 + ((lid >> 3) & 1);
                uint32_t sw = sw128((uint32_t)(n * 128 + kb * 16));
                uint32_t bh[4], bl[4];
                ldsm4(bh, stg + 16384 + sw);
                ldsm4(bl, stg + 49152 + sw);
                #pragma unroll
                for (int mi = 0; mi < 4; mi++) {
                    mma_f16(acc[mi][2 * nj],     a[mi], bh);
                    mma_f16(acc[mi][2 * nj + 1], a[mi], bh + 2);
                    mma_f16(acc[mi][2 * nj],     a[mi], bl);
                    mma_f16(acc[mi][2 * nj + 1], a[mi], bl + 2);
                }
            }
        }
        __syncthreads();      // buffer free before next prefetch overwrites it
    }
    CP_WAIT0();

    // ---- epilogue: bias + ReLU -> scratch fp32 [b][pixel][512] ----
    float* outp = (float*)(g_scratch + OUT_OFF) + soff;
    const int mb = m0 + warp_m * 64;
    const int nb = n0 + warp_n * 64;
    const int r = lid >> 2, c2 = (lid & 3) * 2;
    #pragma unroll
    for (int ni = 0; ni < 8; ni++) {
        float2 bv = *(const float2*)(bias + nb + ni * 8 + c2);
        #pragma unroll
        for (int mi = 0; mi < 4; mi++) {
            float* p0 = outp + (size_t)(bHW + mb + mi * 16 + r) * SH_C + nb + ni * 8 + c2;
            float* p1 = p0 + 8 * SH_C;
            float2 v0, v1;
            v0.x = fmaxf(acc[mi][ni][0] + bv.x, 0.f);
            v0.y = fmaxf(acc[mi][ni][1] + bv.y, 0.f);
            v1.x = fmaxf(acc[mi][ni][2] + bv.x, 0.f);
            v1.y = fmaxf(acc[mi][ni][3] + bv.y, 0.f);
            *(float2*)p0 = v0;
            *(float2*)p1 = v1;
        }
    }
}

// ---------------------------------------------------------------------------
// Stage 2: fused 1x1 heads + softmax + scatter
// ---------------------------------------------------------------------------
__global__ __launch_bounds__(128) void head_kernel(
    size_t soff,
    const float* __restrict__ w_cls, const float* __restrict__ b_cls,
    const float* __restrict__ w_delta, const float* __restrict__ b_delta,
    float* __restrict__ out, int HW, int aoff)
{
    __shared__ float ws[SH_C * 18];
    __shared__ float bs[18];
    const int tid = threadIdx.x;
    for (int i = tid; i < SH_C * 6; i += 128) {
        int c = i / 6, j = i % 6;
        ws[c * 18 + j] = w_cls[i];
    }
    for (int i = tid; i < SH_C * 12; i += 128) {
        int c = i / 12, j = i % 12;
        ws[c * 18 + 6 + j] = w_delta[i];
    }
    if (tid < 6)       bs[tid] = b_cls[tid];
    else if (tid < 18) bs[tid] = b_delta[tid - 6];
    __syncthreads();

    const int m = blockIdx.x * 128 + tid;
    const int b = blockIdx.z;
    const float* row = (const float*)(g_scratch + OUT_OFF) + soff + ((size_t)b * HW + m) * SH_C;

    float acc[18];
    #pragma unroll
    for (int j = 0; j < 18; j++) acc[j] = bs[j];

    #pragma unroll 4
    for (int c = 0; c < SH_C; c += 4) {
        float4 s = *(const float4*)(row + c);
        float sv[4] = {s.x, s.y, s.z, s.w};
        #pragma unroll
        for (int e = 0; e < 4; e++) {
            const float* wrow = &ws[(c + e) * 18];
            #pragma unroll
            for (int j = 0; j < 18; j++) acc[j] += sv[e] * wrow[j];
        }
    }

    float* out_logits = out;
    float* out_probs  = out + (size_t)BATCHN * A_TOTAL * 2;
    float* out_deltas = out + (size_t)2 * BATCHN * A_TOTAL * 2;

    #pragma unroll
    for (int rr = 0; rr < 3; rr++) {
        float l0 = acc[2 * rr], l1 = acc[2 * rr + 1];
        size_t a = (size_t)b * A_TOTAL + (size_t)aoff + (size_t)m * 3 + rr;
        out_logits[a * 2 + 0] = l0;
        out_logits[a * 2 + 1] = l1;
        float mx = fmaxf(l0, l1);
        float e0 = __expf(l0 - mx), e1 = __expf(l1 - mx);
        float inv = 1.0f / (e0 + e1);
        out_probs[a * 2 + 0] = e0 * inv;
        out_probs[a * 2 + 1] = e1 * inv;
        #pragma unroll
        for (int k = 0; k < 4; k++)
            out_deltas[a * 4 + k] = acc[6 + 4 * rr + k];
    }
}

// ---------------------------------------------------------------------------
extern "C" void kernel_launch(void* const* d_in, const int* in_sizes, int n_in,
                              void* d_out, int out_size)
{
    const float* feats[NLEV];
    for (int i = 0; i < NLEV; i++) feats[i] = (const float*)d_in[i];
    const float* w_shared = (const float*)d_in[5];
    const float* b_shared = (const float*)d_in[6];
    const float* w_cls    = (const float*)d_in[7];
    const float* b_cls    = (const float*)d_in[8];
    const float* w_delta  = (const float*)d_in[9];
    const float* b_delta  = (const float*)d_in[10];
    float* out = (float*)d_out;

    static const int    hs[NLEV]    = {256, 128, 64, 32, 16};
    static const int    logw[NLEV]  = {8, 7, 6, 5, 4};
    static const size_t soff[NLEV]  = {0, 67108864, 83886080, 88080384, 89128960};
    static const size_t feoff[NLEV] = {0, 33554432, 41943040, 44040192, 44564480};
    static const int    aoff[NLEV]  = {0, 196608, 245760, 258048, 261120};

    static bool attr_set = false;
    if (!attr_set) {
        cudaFuncSetAttribute(conv3_mma, cudaFuncAttributeMaxDynamicSharedMemorySize, SMEM_TOTAL);
        attr_set = true;
    }

    // launch 0: fused prep (so launch index 5 = conv L0 for ncu -s 5)
    split_all<<<(F_TOTAL + W_TOTAL + 255) / 256, 256>>>(
        feats[0], feats[1], feats[2], feats[3], feats[4], w_shared);

    // launches 1..5: conv, small levels first (L0 lands at index 5)
    for (int l = NLEV - 1; l >= 0; l--) {
        int HW = hs[l] * hs[l];
        dim3 g(HW / 128, SH_C / 256, BATCHN);
        conv3_mma<<<g, 256, SMEM_TOTAL>>>(feoff[l], soff[l], b_shared, hs[l], logw[l]);
    }
    // heads
    for (int l = 0; l < NLEV; l++) {
        int HW = hs[l] * hs[l];
        dim3 g(HW / 128, 1, BATCHN);
        head_kernel<<<g, 128>>>(soff[l], w_cls, b_cls, w_delta, b_delta, out, HW, aoff[l]);
    }
}

// round 7
// speedup vs baseline: 14.3379x; 2.0980x over previous
#include <cuda_runtime.h>
#include <cuda_fp16.h>
#include <cstdint>

#define FPN_C 256
#define SH_C  512
#define NLEV  5
#define BATCHN 2
#define A_TOTAL 261888

// ---------------- scratch layout (bytes) ----------------
// conv activations fp16 : [0, 178,782,208)
// feat fp16             : [FH,  +89,391,104)
// weightT fp16          : [WH,  +2,359,296)   [tap][cout=512][cin=256]
#define OUT_OFF 0
#define FH_OFF  178782208ULL
#define WH_OFF  268173312ULL
__device__ __align__(4096) unsigned char g_scratch[270532608];

// ---------------- PTX helpers ----------------
__device__ __forceinline__ uint32_t smem_u32(const void* p) {
    uint32_t a;
    asm("{ .reg .u64 t; cvta.to.shared.u64 t, %1; cvt.u32.u64 %0, t; }" : "=r"(a) : "l"(p));
    return a;
}
__device__ __forceinline__ void cp16(uint32_t sa, const void* g, uint32_t srcsz) {
    asm volatile("cp.async.cg.shared.global [%0], [%1], 16, %2;" :: "r"(sa), "l"(g), "r"(srcsz));
}
#define CP_COMMIT() asm volatile("cp.async.commit_group;" ::: "memory")
#define CP_WAIT1()  asm volatile("cp.async.wait_group 1;" ::: "memory")
#define CP_WAIT0()  asm volatile("cp.async.wait_group 0;" ::: "memory")

__device__ __forceinline__ void ldsm4(uint32_t* r, uint32_t a) {
    asm volatile("ldmatrix.sync.aligned.m8n8.x4.shared.b16 {%0,%1,%2,%3}, [%4];"
        : "=r"(r[0]), "=r"(r[1]), "=r"(r[2]), "=r"(r[3]) : "r"(a));
}
__device__ __forceinline__ void mma_f16(float* d, const uint32_t* a, const uint32_t* b) {
    asm volatile("mma.sync.aligned.m16n8k16.row.col.f32.f16.f16.f32 "
        "{%0,%1,%2,%3}, {%4,%5,%6,%7}, {%8,%9}, {%0,%1,%2,%3};"
        : "+f"(d[0]), "+f"(d[1]), "+f"(d[2]), "+f"(d[3])
        : "r"(a[0]), "r"(a[1]), "r"(a[2]), "r"(a[3]), "r"(b[0]), "r"(b[1]));
}
__device__ __forceinline__ uint32_t sw128(uint32_t off) {
    return off ^ ((off >> 3) & 0x70);
}

// stage: A[0,16K) B[16K,48K)
#define STAGE_BYTES 49152
#define NSTAGE 3
#define SMEM_TOTAL (NSTAGE * STAGE_BYTES)

// ---------------- level decode tables ----------------
__constant__ int c_logw[NLEV]    = {8, 7, 6, 5, 4};
__constant__ int c_cstart[NLEV]  = {0, 2048, 2560, 2688, 2720};   // conv CTA range start
__constant__ int c_xbsh[NLEV]    = {9, 7, 5, 3, 1};               // log2(HW/128)
__constant__ int c_hstart[NLEV]  = {0, 512, 640, 672, 680};       // head block range start
__constant__ int c_aoff[NLEV]    = {0, 196608, 245760, 258048, 261120};
__constant__ unsigned long long c_soff[NLEV] =
    {0, 67108864ULL, 83886080ULL, 88080384ULL, 89128960ULL};
__constant__ unsigned long long c_feoff[NLEV] =
    {0, 33554432ULL, 41943040ULL, 44040192ULL, 44564480ULL};
#define CONV_CTAS 2728
#define HEAD_BLKS 682

__global__ void noop_pad() {}

// ---------------------------------------------------------------------------
// Fused prep: feats fp32 -> fp16 rn, weights fp32 -> transposed fp16 rn.
// ---------------------------------------------------------------------------
#define F_TOTAL 44695552
#define W_TOTAL 1179648
__global__ __launch_bounds__(256) void split_all(
    const float* __restrict__ f0, const float* __restrict__ f1,
    const float* __restrict__ f2, const float* __restrict__ f3,
    const float* __restrict__ f4, const float* __restrict__ w)
{
    int i = blockIdx.x * 256 + threadIdx.x;
    if (i < F_TOTAL) {
        const float* src;
        int off;
        if (i < 33554432)      { src = f0; off = 0; }
        else if (i < 41943040) { src = f1; off = 33554432; }
        else if (i < 44040192) { src = f2; off = 41943040; }
        else if (i < 44564480) { src = f3; off = 44040192; }
        else                   { src = f4; off = 44564480; }
        ((__half*)(g_scratch + FH_OFF))[i] = __float2half_rn(src[i - off]);
    } else if (i < F_TOTAL + W_TOTAL) {
        int j = i - F_TOTAL;
        int tap = j >> 17;
        int rem = j & 131071;
        int cin = rem >> 9, cout = rem & 511;
        size_t o = ((size_t)(tap * SH_C + cout) << 8) + cin;
        ((__half*)(g_scratch + WH_OFF))[o] = __float2half_rn(w[j]);
    }
}

// ---------------------------------------------------------------------------
// Stage 1: 3x3 conv 256->512 + bias + ReLU. Single-pass fp16 HMMA.
// One launch over all levels (CTA ranges decode the level).
// CTA: M=128 pixels x N=256 couts; 8 warps as 2(M) x 4(N), warp tile 64x64.
// K = 9 taps x 256 cin, kchunk = 64; 3-stage cp.async pipeline, 1 sync/iter.
// ---------------------------------------------------------------------------
__global__ __launch_bounds__(256, 1) void conv3_mma(const float* __restrict__ bias)
{
    extern __shared__ __align__(1024) char smem[];
    const uint32_t sbase = smem_u32(smem);
    const int tid = threadIdx.x;
    const int wid = tid >> 5, lid = tid & 31;
    const int warp_m = wid >> 2;
    const int warp_n = wid & 3;

    // ---- decode level / tile ----
    const int bid = blockIdx.x;
    const int l = (bid >= 2048) + (bid >= 2560) + (bid >= 2688) + (bid >= 2720);
    const int logW = c_logw[l];
    const int H = 1 << logW, W = H, HW = H << logW;
    int r0 = bid - c_cstart[l];
    const int m0 = (r0 & ((1 << c_xbsh[l]) - 1)) << 7;
    r0 >>= c_xbsh[l];
    const int n0 = (r0 & 1) << 8;
    const int b = r0 >> 1;
    const int bHW = b * HW;

    const __half* fh = (const __half*)(g_scratch + FH_OFF) + c_feoff[l];
    const __half* wh = (const __half*)(g_scratch + WH_OFF);

    float acc[4][8][4];
    #pragma unroll
    for (int i = 0; i < 4; i++)
        #pragma unroll
        for (int j = 0; j < 8; j++)
            #pragma unroll
            for (int k = 0; k < 4; k++) acc[i][j][k] = 0.0f;

    // ---- async loader for iteration it = tap*4 + kc ----
    auto load_stage = [&](int it) {
        const int tap = it >> 2, kc = it & 3;
        const int dy = tap / 3 - 1, dx = tap % 3 - 1;
        const uint32_t stg = sbase + (it % NSTAGE) * STAGE_BYTES;
        // A: 128 rows x 8 chunks of 16B
        #pragma unroll
        for (int j = 0; j < 4; j++) {
            int c = tid + 256 * j;
            int r = c >> 3, col8 = c & 7;
            int m = m0 + r;
            int y = m >> logW, x = m & (W - 1);
            int iy = y + dy, ix = x + dx;
            bool inb = ((unsigned)iy < (unsigned)H) && ((unsigned)ix < (unsigned)W);
            int pix = inb ? ((iy << logW) + ix) : 0;
            const __half* src = fh + (((size_t)(bHW + pix)) << 8) + (kc << 6) + (col8 << 3);
            cp16(stg + sw128(r * 128 + col8 * 16), src, inb ? 16u : 0u);
        }
        // B: 256 rows x 8 chunks of 16B
        #pragma unroll
        for (int j = 0; j < 8; j++) {
            int c = tid + 256 * j;
            int r = (c >> 3) & 255, col8 = c & 7;
            const __half* src = wh +
                (((size_t)(tap * SH_C + n0 + r)) << 8) + (kc << 6) + (col8 << 3);
            cp16(stg + 16384 + sw128(r * 128 + col8 * 16), src, 16u);
        }
    };

    load_stage(0); CP_COMMIT();
    load_stage(1); CP_COMMIT();

    for (int it = 0; it < 36; ++it) {
        CP_WAIT1();            // in-order groups: stage `it` complete
        __syncthreads();       // all loads visible; previous buffer free

        const uint32_t stg = sbase + (it % NSTAGE) * STAGE_BYTES;
        #pragma unroll
        for (int ks = 0; ks < 4; ks++) {
            uint32_t a[4][4];
            #pragma unroll
            for (int mi = 0; mi < 4; mi++) {
                int m = warp_m * 64 + mi * 16 + (lid & 15);
                int kb = ks * 2 + (lid >> 4);
                ldsm4(a[mi], stg + sw128((uint32_t)(m * 128 + kb * 16)));
            }
            #pragma unroll
            for (int nj = 0; nj < 4; nj++) {
                int n = warp_n * 64 + nj * 16 + (lid & 7) + ((lid >> 4) << 3);
                int kb = ks * 2 + ((lid >> 3) & 1);
                uint32_t bh[4];
                ldsm4(bh, stg + 16384 + sw128((uint32_t)(n * 128 + kb * 16)));
                #pragma unroll
                for (int mi = 0; mi < 4; mi++) {
                    mma_f16(acc[mi][2 * nj],     a[mi], bh);
                    mma_f16(acc[mi][2 * nj + 1], a[mi], bh + 2);
                }
            }
        }
        if (it + 2 < 36) load_stage(it + 2);
        CP_COMMIT();           // uniform group count
    }
    CP_WAIT0();

    // ---- epilogue: bias + ReLU -> scratch fp16 [b][pixel][512] ----
    __half* outp = (__half*)(g_scratch + OUT_OFF) + c_soff[l];
    const int mb = m0 + warp_m * 64;
    const int nb = n0 + warp_n * 64;
    const int rr = lid >> 2, c2 = (lid & 3) * 2;
    #pragma unroll
    for (int ni = 0; ni < 8; ni++) {
        float2 bv = *(const float2*)(bias + nb + ni * 8 + c2);
        #pragma unroll
        for (int mi = 0; mi < 4; mi++) {
            __half* p0 = outp + (size_t)(bHW + mb + mi * 16 + rr) * SH_C + nb + ni * 8 + c2;
            __half* p1 = p0 + 8 * SH_C;
            *(__half2*)p0 = __floats2half2_rn(fmaxf(acc[mi][ni][0] + bv.x, 0.f),
                                              fmaxf(acc[mi][ni][1] + bv.y, 0.f));
            *(__half2*)p1 = __floats2half2_rn(fmaxf(acc[mi][ni][2] + bv.x, 0.f),
                                              fmaxf(acc[mi][ni][3] + bv.y, 0.f));
        }
    }
}

// ---------------------------------------------------------------------------
// Stage 2: fused 1x1 heads + softmax + scatter. One launch over all levels.
// ---------------------------------------------------------------------------
__global__ __launch_bounds__(128) void head_kernel(
    const float* __restrict__ w_cls, const float* __restrict__ b_cls,
    const float* __restrict__ w_delta, const float* __restrict__ b_delta,
    float* __restrict__ out)
{
    __shared__ float ws[SH_C * 18];
    __shared__ float bs[18];
    const int tid = threadIdx.x;
    for (int i = tid; i < SH_C * 6; i += 128) {
        int c = i / 6, j = i % 6;
        ws[c * 18 + j] = w_cls[i];
    }
    for (int i = tid; i < SH_C * 12; i += 128) {
        int c = i / 12, j = i % 12;
        ws[c * 18 + 6 + j] = w_delta[i];
    }
    if (tid < 6)       bs[tid] = b_cls[tid];
    else if (tid < 18) bs[tid] = b_delta[tid - 6];
    __syncthreads();

    const int bid = blockIdx.x;
    const int l = (bid >= 512) + (bid >= 640) + (bid >= 672) + (bid >= 680);
    const int logW = c_logw[l];
    const int HW = 1 << (2 * logW);
    const int m = ((bid - c_hstart[l]) << 7) + tid;
    const int b = blockIdx.z;
    const __half* row = (const __half*)(g_scratch + OUT_OFF) + c_soff[l]
                        + ((size_t)b * HW + m) * SH_C;

    float acc[18];
    #pragma unroll
    for (int j = 0; j < 18; j++) acc[j] = bs[j];

    #pragma unroll 2
    for (int c = 0; c < SH_C; c += 8) {
        uint4 u = *(const uint4*)(row + c);
        float2 s[4];
        s[0] = __half22float2(*(__half2*)&u.x);
        s[1] = __half22float2(*(__half2*)&u.y);
        s[2] = __half22float2(*(__half2*)&u.z);
        s[3] = __half22float2(*(__half2*)&u.w);
        #pragma unroll
        for (int e = 0; e < 4; e++) {
            const float* w0 = &ws[(c + 2 * e) * 18];
            const float* w1 = w0 + 18;
            #pragma unroll
            for (int j = 0; j < 18; j++)
                acc[j] += s[e].x * w0[j] + s[e].y * w1[j];
        }
    }

    float* out_logits = out;
    float* out_probs  = out + (size_t)BATCHN * A_TOTAL * 2;
    float* out_deltas = out + (size_t)2 * BATCHN * A_TOTAL * 2;

    #pragma unroll
    for (int rr = 0; rr < 3; rr++) {
        float l0 = acc[2 * rr], l1 = acc[2 * rr + 1];
        size_t a = (size_t)b * A_TOTAL + (size_t)c_aoff[l] + (size_t)m * 3 + rr;
        out_logits[a * 2 + 0] = l0;
        out_logits[a * 2 + 1] = l1;
        float mx = fmaxf(l0, l1);
        float e0 = __expf(l0 - mx), e1 = __expf(l1 - mx);
        float inv = 1.0f / (e0 + e1);
        out_probs[a * 2 + 0] = e0 * inv;
        out_probs[a * 2 + 1] = e1 * inv;
        #pragma unroll
        for (int k = 0; k < 4; k++)
            out_deltas[a * 4 + k] = acc[6 + 4 * rr + k];
    }
}

// ---------------------------------------------------------------------------
extern "C" void kernel_launch(void* const* d_in, const int* in_sizes, int n_in,
                              void* d_out, int out_size)
{
    const float* feats[NLEV];
    for (int i = 0; i < NLEV; i++) feats[i] = (const float*)d_in[i];
    const float* w_shared = (const float*)d_in[5];
    const float* b_shared = (const float*)d_in[6];
    const float* w_cls    = (const float*)d_in[7];
    const float* b_cls    = (const float*)d_in[8];
    const float* w_delta  = (const float*)d_in[9];
    const float* b_delta  = (const float*)d_in[10];
    float* out = (float*)d_out;

    static bool attr_set = false;
    if (!attr_set) {
        cudaFuncSetAttribute(conv3_mma, cudaFuncAttributeMaxDynamicSharedMemorySize, SMEM_TOTAL);
        attr_set = true;
    }

    // 4 launches/call: pad(0), split(1), conv(2), head(3) -> ncu -s 5 = conv (call 2)
    noop_pad<<<1, 32>>>();
    split_all<<<(F_TOTAL + W_TOTAL + 255) / 256, 256>>>(
        feats[0], feats[1], feats[2], feats[3], feats[4], w_shared);
    conv3_mma<<<CONV_CTAS, 256, SMEM_TOTAL>>>(b_shared);
    {
        dim3 g(HEAD_BLKS, 1, BATCHN);
        head_kernel<<<g, 128>>>(w_cls, b_cls, w_delta, b_delta, out);
    }
}

// round 9
// speedup vs baseline: 15.7095x; 1.0957x over previous
#include <cuda_runtime.h>
#include <cuda_fp16.h>
#include <cstdint>

#define FPN_C 256
#define SH_C  512
#define NLEV  5
#define BATCHN 2
#define A_TOTAL 261888

// ---------------- scratch layout (bytes) ----------------
// conv activations fp16 : [0, 178,782,208)
// feat fp16             : [FH,  +89,391,104)
// weightT fp16          : [WH,  +2,359,296)   [tap][cout=512][cin=256]
// head weight fp16      : [WHD, +24,576)      [24][512]  (cls0-5 | delta6-17 | pad)
#define OUT_OFF 0
#define FH_OFF  178782208ULL
#define WH_OFF  268173312ULL
#define WHD_OFF 270532608ULL
__device__ __align__(4096) unsigned char g_scratch[270557184];

// ---------------- PTX helpers ----------------
__device__ __forceinline__ uint32_t smem_u32(const void* p) {
    uint32_t a;
    asm("{ .reg .u64 t; cvta.to.shared.u64 t, %1; cvt.u32.u64 %0, t; }" : "=r"(a) : "l"(p));
    return a;
}
__device__ __forceinline__ void cp16(uint32_t sa, const void* g, uint32_t srcsz) {
    asm volatile("cp.async.cg.shared.global [%0], [%1], 16, %2;" :: "r"(sa), "l"(g), "r"(srcsz));
}
#define CP_COMMIT() asm volatile("cp.async.commit_group;" ::: "memory")
#define CP_WAIT0()  asm volatile("cp.async.wait_group 0;" ::: "memory")
#define CP_WAIT1()  asm volatile("cp.async.wait_group 1;" ::: "memory")

__device__ __forceinline__ void ldsm4(uint32_t* r, uint32_t a) {
    asm volatile("ldmatrix.sync.aligned.m8n8.x4.shared.b16 {%0,%1,%2,%3}, [%4];"
        : "=r"(r[0]), "=r"(r[1]), "=r"(r[2]), "=r"(r[3]) : "r"(a));
}
__device__ __forceinline__ void ldsm2(uint32_t* r, uint32_t a) {
    asm volatile("ldmatrix.sync.aligned.m8n8.x2.shared.b16 {%0,%1}, [%2];"
        : "=r"(r[0]), "=r"(r[1]) : "r"(a));
}
__device__ __forceinline__ void mma_f16(float* d, const uint32_t* a, const uint32_t* b) {
    asm volatile("mma.sync.aligned.m16n8k16.row.col.f32.f16.f16.f32 "
        "{%0,%1,%2,%3}, {%4,%5,%6,%7}, {%8,%9}, {%0,%1,%2,%3};"
        : "+f"(d[0]), "+f"(d[1]), "+f"(d[2]), "+f"(d[3])
        : "r"(a[0]), "r"(a[1]), "r"(a[2]), "r"(a[3]), "r"(b[0]), "r"(b[1]));
}
__device__ __forceinline__ uint32_t sw128(uint32_t off) {
    return off ^ ((off >> 3) & 0x70);
}

// conv stage: A[0,16K) B[16K,48K); 4 stages
#define STAGE_BYTES 49152
#define NSTAGE 4
#define CONV_SMEM (NSTAGE * STAGE_BYTES)

// head smem: W[0,24K), A stages 3 x 32K
#define HW_SMEM_W 24576
#define HA_STAGE  32768
#define HEAD_SMEM (HW_SMEM_W + 3 * HA_STAGE)

// ---------------- level decode tables ----------------
__constant__ int c_logw[NLEV]   = {8, 7, 6, 5, 4};
__constant__ int c_cstart[NLEV] = {0, 2048, 2560, 2688, 2720};
__constant__ int c_xbsh[NLEV]   = {9, 7, 5, 3, 1};
__constant__ int c_hstart[NLEV] = {0, 512, 640, 672, 680};
__constant__ int c_aoff[NLEV]   = {0, 196608, 245760, 258048, 261120};
__constant__ unsigned long long c_soff[NLEV] =
    {0, 67108864ULL, 83886080ULL, 88080384ULL, 89128960ULL};
__constant__ unsigned long long c_feoff[NLEV] =
    {0, 33554432ULL, 41943040ULL, 44040192ULL, 44564480ULL};
#define CONV_CTAS 2728
#define HEAD_BLKS 682

__global__ void noop_pad() {}

// ---------------------------------------------------------------------------
// Fused prep: feats->fp16, conv weights->transposed fp16, head weights->[24][512] fp16
// ---------------------------------------------------------------------------
#define F_TOTAL 44695552
#define W_TOTAL 1179648
#define WHD_TOTAL 12288
__global__ __launch_bounds__(256) void split_all(
    const float* __restrict__ f0, const float* __restrict__ f1,
    const float* __restrict__ f2, const float* __restrict__ f3,
    const float* __restrict__ f4, const float* __restrict__ w,
    const float* __restrict__ w_cls, const float* __restrict__ w_delta)
{
    int i = blockIdx.x * 256 + threadIdx.x;
    if (i < F_TOTAL) {
        const float* src;
        int off;
        if (i < 33554432)      { src = f0; off = 0; }
        else if (i < 41943040) { src = f1; off = 33554432; }
        else if (i < 44040192) { src = f2; off = 41943040; }
        else if (i < 44564480) { src = f3; off = 44040192; }
        else                   { src = f4; off = 44564480; }
        ((__half*)(g_scratch + FH_OFF))[i] = __float2half_rn(src[i - off]);
    } else if (i < F_TOTAL + W_TOTAL) {
        int j = i - F_TOTAL;
        int tap = j >> 17;
        int rem = j & 131071;
        int cin = rem >> 9, cout = rem & 511;
        size_t o = ((size_t)(tap * SH_C + cout) << 8) + cin;
        ((__half*)(g_scratch + WH_OFF))[o] = __float2half_rn(w[j]);
    } else if (i < F_TOTAL + W_TOTAL + WHD_TOTAL) {
        int j = i - F_TOTAL - W_TOTAL;
        int n = j >> 9, k = j & 511;
        float v = 0.f;
        if (n < 6)       v = w_cls[k * 6 + n];
        else if (n < 18) v = w_delta[k * 12 + (n - 6)];
        ((__half*)(g_scratch + WHD_OFF))[j] = __float2half_rn(v);
    }
}

// ---------------------------------------------------------------------------
// Stage 1: 3x3 conv 256->512 + bias + ReLU. Single-pass fp16 HMMA.
// 4-stage cp.async pipeline, ONE barrier per 2 K-iterations.
// ---------------------------------------------------------------------------
__global__ __launch_bounds__(256, 1) void conv3_mma(const float* __restrict__ bias)
{
    extern __shared__ __align__(1024) char smem[];
    const uint32_t sbase = smem_u32(smem);
    const int tid = threadIdx.x;
    const int wid = tid >> 5, lid = tid & 31;
    const int warp_m = wid >> 2;
    const int warp_n = wid & 3;

    const int bid = blockIdx.x;
    const int l = (bid >= 2048) + (bid >= 2560) + (bid >= 2688) + (bid >= 2720);
    const int logW = c_logw[l];
    const int H = 1 << logW, W = H, HW = H << logW;
    int r0 = bid - c_cstart[l];
    const int m0 = (r0 & ((1 << c_xbsh[l]) - 1)) << 7;
    r0 >>= c_xbsh[l];
    const int n0 = (r0 & 1) << 8;
    const int b = r0 >> 1;
    const int bHW = b * HW;

    const __half* fh = (const __half*)(g_scratch + FH_OFF) + c_feoff[l];
    const __half* wh = (const __half*)(g_scratch + WH_OFF);

    float acc[4][8][4];
    #pragma unroll
    for (int i = 0; i < 4; i++)
        #pragma unroll
        for (int j = 0; j < 8; j++)
            #pragma unroll
            for (int k = 0; k < 4; k++) acc[i][j][k] = 0.0f;

    auto load_stage = [&](int it) {
        const int tap = it >> 2, kc = it & 3;
        const int dy = tap / 3 - 1, dx = tap % 3 - 1;
        const uint32_t stg = sbase + (it % NSTAGE) * STAGE_BYTES;
        #pragma unroll
        for (int j = 0; j < 4; j++) {
            int c = tid + 256 * j;
            int r = c >> 3, col8 = c & 7;
            int m = m0 + r;
            int y = m >> logW, x = m & (W - 1);
            int iy = y + dy, ix = x + dx;
            bool inb = ((unsigned)iy < (unsigned)H) && ((unsigned)ix < (unsigned)W);
            int pix = inb ? ((iy << logW) + ix) : 0;
            const __half* src = fh + (((size_t)(bHW + pix)) << 8) + (kc << 6) + (col8 << 3);
            cp16(stg + sw128(r * 128 + col8 * 16), src, inb ? 16u : 0u);
        }
        #pragma unroll
        for (int j = 0; j < 8; j++) {
            int c = tid + 256 * j;
            int r = (c >> 3) & 255, col8 = c & 7;
            const __half* src = wh +
                (((size_t)(tap * SH_C + n0 + r)) << 8) + (kc << 6) + (col8 << 3);
            cp16(stg + 16384 + sw128(r * 128 + col8 * 16), src, 16u);
        }
    };

    auto compute = [&](int it) {
        const uint32_t stg = sbase + (it % NSTAGE) * STAGE_BYTES;
        #pragma unroll
        for (int ks = 0; ks < 4; ks++) {
            uint32_t a[4][4];
            #pragma unroll
            for (int mi = 0; mi < 4; mi++) {
                int m = warp_m * 64 + mi * 16 + (lid & 15);
                int kb = ks * 2 + (lid >> 4);
                ldsm4(a[mi], stg + sw128((uint32_t)(m * 128 + kb * 16)));
            }
            #pragma unroll
            for (int nj = 0; nj < 4; nj++) {
                int n = warp_n * 64 + nj * 16 + (lid & 7) + ((lid >> 4) << 3);
                int kb = ks * 2 + ((lid >> 3) & 1);
                uint32_t bh[4];
                ldsm4(bh, stg + 16384 + sw128((uint32_t)(n * 128 + kb * 16)));
                #pragma unroll
                for (int mi = 0; mi < 4; mi++) {
                    mma_f16(acc[mi][2 * nj],     a[mi], bh);
                    mma_f16(acc[mi][2 * nj + 1], a[mi], bh + 2);
                }
            }
        }
    };

    load_stage(0); CP_COMMIT();
    load_stage(1); CP_COMMIT();

    for (int it = 0; it < 36; it += 2) {
        CP_WAIT0();            // stages it, it+1 landed (nothing newer in flight)
        __syncthreads();       // data visible; stages (it+2)%4,(it+3)%4 free
        if (it + 2 < 36) { load_stage(it + 2); CP_COMMIT(); }
        if (it + 3 < 36) { load_stage(it + 3); CP_COMMIT(); }
        compute(it);
        compute(it + 1);
    }

    // ---- epilogue: bias + ReLU -> scratch fp16 [b][pixel][512] ----
    __half* outp = (__half*)(g_scratch + OUT_OFF) + c_soff[l];
    const int mb = m0 + warp_m * 64;
    const int nb = n0 + warp_n * 64;
    const int rr = lid >> 2, c2 = (lid & 3) * 2;
    #pragma unroll
    for (int ni = 0; ni < 8; ni++) {
        float2 bv = *(const float2*)(bias + nb + ni * 8 + c2);
        #pragma unroll
        for (int mi = 0; mi < 4; mi++) {
            __half* p0 = outp + (size_t)(bHW + mb + mi * 16 + rr) * SH_C + nb + ni * 8 + c2;
            __half* p1 = p0 + 8 * SH_C;
            *(__half2*)p0 = __floats2half2_rn(fmaxf(acc[mi][ni][0] + bv.x, 0.f),
                                              fmaxf(acc[mi][ni][1] + bv.y, 0.f));
            *(__half2*)p1 = __floats2half2_rn(fmaxf(acc[mi][ni][2] + bv.x, 0.f),
                                              fmaxf(acc[mi][ni][3] + bv.y, 0.f));
        }
    }
}

// ---------------------------------------------------------------------------
// Stage 2: HMMA head. out[256pix, 24] = act[256,512] x Whead^T, fused
// softmax + scatter. 8 warps x 32 pixels; K staged 64 at a time.
// ---------------------------------------------------------------------------
__global__ __launch_bounds__(256, 1) void head_mma(
    const float* __restrict__ b_cls, const float* __restrict__ b_delta,
    float* __restrict__ out)
{
    extern __shared__ __align__(1024) char smem[];
    const uint32_t sW = smem_u32(smem);
    const uint32_t sA = sW + HW_SMEM_W;
    const int tid = threadIdx.x;
    const int wid = tid >> 5, lid = tid & 31;

    const int bid = blockIdx.x;
    const int l = (bid >= 512) + (bid >= 640) + (bid >= 672) + (bid >= 680);
    const int logW = c_logw[l];
    const int HW = 1 << (2 * logW);
    int r = bid - c_hstart[l];
    const int b = (2 * logW - 8) ? (r >> (2 * logW - 8)) : r;
    const int pix0 = (r << 8) & (HW - 1);

    const __half* act = (const __half*)(g_scratch + OUT_OFF) + c_soff[l]
                        + ((size_t)(b * HW + pix0)) * SH_C;
    const __half* whd = (const __half*)(g_scratch + WHD_OFF);

    // W into smem, swizzled: row n (1024B), 16B chunk c -> chunk c ^ (n&7)
    #pragma unroll
    for (int j = 0; j < 6; j++) {
        int c = tid + 256 * j;
        int n = c >> 6, cir = c & 63;
        cp16(sW + n * 1024 + ((cir ^ (n & 7)) * 16), (const char*)whd + c * 16, 16u);
    }
    CP_COMMIT();

    auto loadA = [&](int kc) {
        const uint32_t stg = sA + (kc % 3) * HA_STAGE;
        #pragma unroll
        for (int j = 0; j < 8; j++) {
            int c = tid + 256 * j;
            int row = c >> 3, col8 = c & 7;
            const __half* src = act + (size_t)row * SH_C + kc * 64 + col8 * 8;
            cp16(stg + sw128(row * 128 + col8 * 16), src, 16u);
        }
    };

    loadA(0); CP_COMMIT();
    loadA(1); CP_COMMIT();

    float acc[2][3][4];
    #pragma unroll
    for (int i = 0; i < 2; i++)
        #pragma unroll
        for (int j = 0; j < 3; j++)
            #pragma unroll
            for (int k = 0; k < 4; k++) acc[i][j][k] = 0.0f;

    const int wm0 = wid * 32;
    for (int kc = 0; kc < 8; ++kc) {
        CP_WAIT1();
        __syncthreads();
        const uint32_t stg = sA + (kc % 3) * HA_STAGE;
        #pragma unroll
        for (int ks = 0; ks < 4; ks++) {
            uint32_t a[2][4];
            #pragma unroll
            for (int mi = 0; mi < 2; mi++) {
                int m = wm0 + mi * 16 + (lid & 15);
                int kb = ks * 2 + (lid >> 4);
                ldsm4(a[mi], stg + sw128((uint32_t)(m * 128 + kb * 16)));
            }
            #pragma unroll
            for (int nf = 0; nf < 3; nf++) {
                int n = nf * 8 + (lid & 7);
                int chunk = kc * 8 + ks * 2 + ((lid >> 3) & 1);
                uint32_t bb[2];
                ldsm2(bb, sW + n * 1024 + ((chunk ^ (n & 7)) * 16));
                #pragma unroll
                for (int mi = 0; mi < 2; mi++)
                    mma_f16(acc[mi][nf], a[mi], bb);
            }
        }
        if (kc + 2 < 8) loadA(kc + 2);
        CP_COMMIT();
        __syncthreads();
    }
    CP_WAIT0();

    // ---- epilogue: bias + softmax + scatter ----
    float* out_logits = out;
    float* out_probs  = out + (size_t)BATCHN * A_TOTAL * 2;
    float* out_deltas = out + (size_t)2 * BATCHN * A_TOTAL * 2;

    const size_t bb0 = (size_t)b * A_TOTAL + c_aoff[l];
    const int r0 = lid >> 2, c2 = (lid & 3) * 2;

    #pragma unroll
    for (int nf = 0; nf < 3; nf++) {
        int c = nf * 8 + c2;
        if (c >= 18) continue;
        float bias0 = c < 6 ? __ldg(b_cls + c) : __ldg(b_delta + c - 6);
        float bias1 = (c + 1) < 6 ? __ldg(b_cls + c + 1) : __ldg(b_delta + c - 5);
        #pragma unroll
        for (int mi = 0; mi < 2; mi++) {
            #pragma unroll
            for (int h = 0; h < 2; h++) {
                int p = pix0 + wm0 + mi * 16 + r0 + 8 * h;
                float v0 = acc[mi][nf][2 * h]     + bias0;
                float v1 = acc[mi][nf][2 * h + 1] + bias1;
                if (c < 6) {
                    size_t a = bb0 + (size_t)p * 3 + (c >> 1);
                    *(float2*)(out_logits + a * 2) = make_float2(v0, v1);
                    float mx = fmaxf(v0, v1);
                    float e0 = __expf(v0 - mx), e1 = __expf(v1 - mx);
                    float inv = 1.0f / (e0 + e1);
                    *(float2*)(out_probs + a * 2) = make_float2(e0 * inv, e1 * inv);
                } else {
                    int d = c - 6;
                    size_t a = bb0 + (size_t)p * 3 + (d >> 2);
                    *(float2*)(out_deltas + a * 4 + (d & 3)) = make_float2(v0, v1);
                }
            }
        }
    }
}

// ---------------------------------------------------------------------------
extern "C" void kernel_launch(void* const* d_in, const int* in_sizes, int n_in,
                              void* d_out, int out_size)
{
    const float* feats[NLEV];
    for (int i = 0; i < NLEV; i++) feats[i] = (const float*)d_in[i];
    const float* w_shared = (const float*)d_in[5];
    const float* b_shared = (const float*)d_in[6];
    const float* w_cls    = (const float*)d_in[7];
    const float* b_cls    = (const float*)d_in[8];
    const float* w_delta  = (const float*)d_in[9];
    const float* b_delta  = (const float*)d_in[10];
    float* out = (float*)d_out;

    static bool attr_set = false;
    if (!attr_set) {
        cudaFuncSetAttribute(conv3_mma, cudaFuncAttributeMaxDynamicSharedMemorySize, CONV_SMEM);
        cudaFuncSetAttribute(head_mma, cudaFuncAttributeMaxDynamicSharedMemorySize, HEAD_SMEM);
        attr_set = true;
    }

    noop_pad<<<1, 32>>>();
    split_all<<<(F_TOTAL + W_TOTAL + WHD_TOTAL + 255) / 256, 256>>>(
        feats[0], feats[1], feats[2], feats[3], feats[4], w_shared, w_cls, w_delta);
    conv3_mma<<<CONV_CTAS, 256, CONV_SMEM>>>(b_shared);
    head_mma<<<HEAD_BLKS, 256, HEAD_SMEM>>>(b_cls, b_delta, out);
}

// round 10
// speedup vs baseline: 16.6789x; 1.0617x over previous
#include <cuda_runtime.h>
#include <cuda_fp16.h>
#include <cstdint>

#define FPN_C 256
#define SH_C  512
#define NLEV  5
#define BATCHN 2
#define A_TOTAL 261888

// ---------------- scratch layout (bytes) ----------------
#define OUT_OFF 0
#define FH_OFF  178782208ULL
#define WH_OFF  268173312ULL
#define WHD_OFF 270532608ULL
__device__ __align__(4096) unsigned char g_scratch[270557184];

// ---------------- PTX helpers ----------------
__device__ __forceinline__ uint32_t smem_u32(const void* p) {
    uint32_t a;
    asm("{ .reg .u64 t; cvta.to.shared.u64 t, %1; cvt.u32.u64 %0, t; }" : "=r"(a) : "l"(p));
    return a;
}
__device__ __forceinline__ void cp16(uint32_t sa, const void* g, uint32_t srcsz) {
    asm volatile("cp.async.cg.shared.global [%0], [%1], 16, %2;" :: "r"(sa), "l"(g), "r"(srcsz));
}
#define CP_COMMIT() asm volatile("cp.async.commit_group;" ::: "memory")
#define CP_WAIT0()  asm volatile("cp.async.wait_group 0;" ::: "memory")
#define CP_WAIT1()  asm volatile("cp.async.wait_group 1;" ::: "memory")

__device__ __forceinline__ void ldsm4(uint32_t* r, uint32_t a) {
    asm volatile("ldmatrix.sync.aligned.m8n8.x4.shared.b16 {%0,%1,%2,%3}, [%4];"
        : "=r"(r[0]), "=r"(r[1]), "=r"(r[2]), "=r"(r[3]) : "r"(a));
}
__device__ __forceinline__ void ldsm2(uint32_t* r, uint32_t a) {
    asm volatile("ldmatrix.sync.aligned.m8n8.x2.shared.b16 {%0,%1}, [%2];"
        : "=r"(r[0]), "=r"(r[1]) : "r"(a));
}
__device__ __forceinline__ void mma_f16(float* d, const uint32_t* a, const uint32_t* b) {
    asm volatile("mma.sync.aligned.m16n8k16.row.col.f32.f16.f16.f32 "
        "{%0,%1,%2,%3}, {%4,%5,%6,%7}, {%8,%9}, {%0,%1,%2,%3};"
        : "+f"(d[0]), "+f"(d[1]), "+f"(d[2]), "+f"(d[3])
        : "r"(a[0]), "r"(a[1]), "r"(a[2]), "r"(a[3]), "r"(b[0]), "r"(b[1]));
}
__device__ __forceinline__ uint32_t sw128(uint32_t off) {
    return off ^ ((off >> 3) & 0x70);
}

// conv stage: A[0,16K) B[16K,32K); 3 stages; 2 CTAs/SM
#define STAGE_BYTES 32768
#define NSTAGE 3
#define CONV_SMEM (NSTAGE * STAGE_BYTES)

// head smem: W[0,24K), A stages 3 x 32K
#define HW_SMEM_W 24576
#define HA_STAGE  32768
#define HEAD_SMEM (HW_SMEM_W + 3 * HA_STAGE)

// ---------------- level decode tables ----------------
__constant__ int c_logw[NLEV]   = {8, 7, 6, 5, 4};
__constant__ int c_cstart[NLEV] = {0, 4096, 5120, 5376, 5440};
__constant__ int c_xbsh[NLEV]   = {9, 7, 5, 3, 1};
__constant__ int c_hstart[NLEV] = {0, 512, 640, 672, 680};
__constant__ int c_aoff[NLEV]   = {0, 196608, 245760, 258048, 261120};
__constant__ unsigned long long c_soff[NLEV] =
    {0, 67108864ULL, 83886080ULL, 88080384ULL, 89128960ULL};
__constant__ unsigned long long c_feoff[NLEV] =
    {0, 33554432ULL, 41943040ULL, 44040192ULL, 44564480ULL};
#define CONV_CTAS 5456
#define HEAD_BLKS 682

__global__ void noop_pad() {}

// ---------------------------------------------------------------------------
// Fused prep (feats vectorized x4): feats->fp16, conv W->[tap][cout][cin] fp16,
// head W->[24][512] fp16.
// ---------------------------------------------------------------------------
#define F_TOTAL 44695552
#define F4 (F_TOTAL / 4)
#define W_TOTAL 1179648
#define WHD_TOTAL 12288
__global__ __launch_bounds__(256) void split_all(
    const float* __restrict__ f0, const float* __restrict__ f1,
    const float* __restrict__ f2, const float* __restrict__ f3,
    const float* __restrict__ f4, const float* __restrict__ w,
    const float* __restrict__ w_cls, const float* __restrict__ w_delta)
{
    int i = blockIdx.x * 256 + threadIdx.x;
    if (i < F4) {
        int base = i << 2;
        const float* src;
        int off;
        if (base < 33554432)      { src = f0; off = 0; }
        else if (base < 41943040) { src = f1; off = 33554432; }
        else if (base < 44040192) { src = f2; off = 41943040; }
        else if (base < 44564480) { src = f3; off = 44040192; }
        else                      { src = f4; off = 44564480; }
        float4 v = *(const float4*)(src + (base - off));
        __half2 h0 = __floats2half2_rn(v.x, v.y);
        __half2 h1 = __floats2half2_rn(v.z, v.w);
        uint2 u;
        u.x = *(uint32_t*)&h0;
        u.y = *(uint32_t*)&h1;
        *(uint2*)((__half*)(g_scratch + FH_OFF) + base) = u;
    } else if (i < F4 + W_TOTAL) {
        int j = i - F4;
        int tap = j >> 17;
        int rem = j & 131071;
        int cin = rem >> 9, cout = rem & 511;
        size_t o = ((size_t)(tap * SH_C + cout) << 8) + cin;
        ((__half*)(g_scratch + WH_OFF))[o] = __float2half_rn(w[j]);
    } else if (i < F4 + W_TOTAL + WHD_TOTAL) {
        int j = i - F4 - W_TOTAL;
        int n = j >> 9, k = j & 511;
        float v = 0.f;
        if (n < 6)       v = w_cls[k * 6 + n];
        else if (n < 18) v = w_delta[k * 12 + (n - 6)];
        ((__half*)(g_scratch + WHD_OFF))[j] = __float2half_rn(v);
    }
}

// ---------------------------------------------------------------------------
// Stage 1: 3x3 conv 256->512 + bias + ReLU. Single-pass fp16 HMMA.
// CTA: M=128 x N=128 (2 CTAs/SM). 8 warps as 2(M) x 4(N), warp tile 64x32.
// K = 9 taps x 256, kchunk=64; 3-stage cp.async, 1 barrier/iter.
// ---------------------------------------------------------------------------
__global__ __launch_bounds__(256, 2) void conv3_mma(const float* __restrict__ bias)
{
    extern __shared__ __align__(1024) char smem[];
    const uint32_t sbase = smem_u32(smem);
    const int tid = threadIdx.x;
    const int wid = tid >> 5, lid = tid & 31;
    const int warp_m = wid >> 2;
    const int warp_n = wid & 3;

    const int bid = blockIdx.x;
    const int l = (bid >= 4096) + (bid >= 5120) + (bid >= 5376) + (bid >= 5440);
    const int logW = c_logw[l];
    const int H = 1 << logW, W = H, HW = H << logW;
    int r0 = bid - c_cstart[l];
    const int m0 = (r0 & ((1 << c_xbsh[l]) - 1)) << 7;
    r0 >>= c_xbsh[l];
    const int n0 = (r0 & 3) << 7;
    const int b = r0 >> 2;
    const int bHW = b * HW;

    const __half* fh = (const __half*)(g_scratch + FH_OFF) + c_feoff[l];
    const __half* wh = (const __half*)(g_scratch + WH_OFF);

    float acc[4][4][4];
    #pragma unroll
    for (int i = 0; i < 4; i++)
        #pragma unroll
        for (int j = 0; j < 4; j++)
            #pragma unroll
            for (int k = 0; k < 4; k++) acc[i][j][k] = 0.0f;

    auto load_stage = [&](int it) {
        const int tap = it >> 2, kc = it & 3;
        const int dy = tap / 3 - 1, dx = tap % 3 - 1;
        const uint32_t stg = sbase + (it % NSTAGE) * STAGE_BYTES;
        // A: 128 rows x 8 chunks of 16B
        #pragma unroll
        for (int j = 0; j < 4; j++) {
            int c = tid + 256 * j;
            int r = c >> 3, col8 = c & 7;
            int m = m0 + r;
            int y = m >> logW, x = m & (W - 1);
            int iy = y + dy, ix = x + dx;
            bool inb = ((unsigned)iy < (unsigned)H) && ((unsigned)ix < (unsigned)W);
            int pix = inb ? ((iy << logW) + ix) : 0;
            const __half* src = fh + (((size_t)(bHW + pix)) << 8) + (kc << 6) + (col8 << 3);
            cp16(stg + sw128(r * 128 + col8 * 16), src, inb ? 16u : 0u);
        }
        // B: 128 rows x 8 chunks of 16B
        #pragma unroll
        for (int j = 0; j < 4; j++) {
            int c = tid + 256 * j;
            int r = c >> 3, col8 = c & 7;
            const __half* src = wh +
                (((size_t)(tap * SH_C + n0 + r)) << 8) + (kc << 6) + (col8 << 3);
            cp16(stg + 16384 + sw128(r * 128 + col8 * 16), src, 16u);
        }
    };

    auto compute = [&](int it) {
        const uint32_t stg = sbase + (it % NSTAGE) * STAGE_BYTES;
        #pragma unroll
        for (int ks = 0; ks < 4; ks++) {
            uint32_t a[4][4];
            #pragma unroll
            for (int mi = 0; mi < 4; mi++) {
                int m = warp_m * 64 + mi * 16 + (lid & 15);
                int kb = ks * 2 + (lid >> 4);
                ldsm4(a[mi], stg + sw128((uint32_t)(m * 128 + kb * 16)));
            }
            #pragma unroll
            for (int nj = 0; nj < 2; nj++) {
                int n = warp_n * 32 + nj * 16 + (lid & 7) + ((lid >> 4) << 3);
                int kb = ks * 2 + ((lid >> 3) & 1);
                uint32_t bh[4];
                ldsm4(bh, stg + 16384 + sw128((uint32_t)(n * 128 + kb * 16)));
                #pragma unroll
                for (int mi = 0; mi < 4; mi++) {
                    mma_f16(acc[mi][2 * nj],     a[mi], bh);
                    mma_f16(acc[mi][2 * nj + 1], a[mi], bh + 2);
                }
            }
        }
    };

    load_stage(0); CP_COMMIT();
    load_stage(1); CP_COMMIT();

    for (int it = 0; it < 36; ++it) {
        CP_WAIT1();            // stage `it` landed (newest, it+1, may fly)
        __syncthreads();       // visible to all; stage (it+2)%3 free
        compute(it);
        if (it + 2 < 36) { load_stage(it + 2); CP_COMMIT(); }
    }
    CP_WAIT0();

    // ---- epilogue: bias + ReLU -> scratch fp16 [b][pixel][512] ----
    __half* outp = (__half*)(g_scratch + OUT_OFF) + c_soff[l];
    const int mb = m0 + warp_m * 64;
    const int nb = n0 + warp_n * 32;
    const int rr = lid >> 2, c2 = (lid & 3) * 2;
    #pragma unroll
    for (int ni = 0; ni < 4; ni++) {
        float2 bv = *(const float2*)(bias + nb + ni * 8 + c2);
        #pragma unroll
        for (int mi = 0; mi < 4; mi++) {
            __half* p0 = outp + (size_t)(bHW + mb + mi * 16 + rr) * SH_C + nb + ni * 8 + c2;
            __half* p1 = p0 + 8 * SH_C;
            *(__half2*)p0 = __floats2half2_rn(fmaxf(acc[mi][ni][0] + bv.x, 0.f),
                                              fmaxf(acc[mi][ni][1] + bv.y, 0.f));
            *(__half2*)p1 = __floats2half2_rn(fmaxf(acc[mi][ni][2] + bv.x, 0.f),
                                              fmaxf(acc[mi][ni][3] + bv.y, 0.f));
        }
    }
}

// ---------------------------------------------------------------------------
// Stage 2: HMMA head (unchanged from R8).
// ---------------------------------------------------------------------------
__global__ __launch_bounds__(256, 1) void head_mma(
    const float* __restrict__ b_cls, const float* __restrict__ b_delta,
    float* __restrict__ out)
{
    extern __shared__ __align__(1024) char smem[];
    const uint32_t sW = smem_u32(smem);
    const uint32_t sA = sW + HW_SMEM_W;
    const int tid = threadIdx.x;
    const int wid = tid >> 5, lid = tid & 31;

    const int bid = blockIdx.x;
    const int l = (bid >= 512) + (bid >= 640) + (bid >= 672) + (bid >= 680);
    const int logW = c_logw[l];
    const int HW = 1 << (2 * logW);
    int r = bid - c_hstart[l];
    const int b = (2 * logW - 8) ? (r >> (2 * logW - 8)) : r;
    const int pix0 = (r << 8) & (HW - 1);

    const __half* act = (const __half*)(g_scratch + OUT_OFF) + c_soff[l]
                        + ((size_t)(b * HW + pix0)) * SH_C;
    const __half* whd = (const __half*)(g_scratch + WHD_OFF);

    #pragma unroll
    for (int j = 0; j < 6; j++) {
        int c = tid + 256 * j;
        int n = c >> 6, cir = c & 63;
        cp16(sW + n * 1024 + ((cir ^ (n & 7)) * 16), (const char*)whd + c * 16, 16u);
    }
    CP_COMMIT();

    auto loadA = [&](int kc) {
        const uint32_t stg = sA + (kc % 3) * HA_STAGE;
        #pragma unroll
        for (int j = 0; j < 8; j++) {
            int c = tid + 256 * j;
            int row = c >> 3, col8 = c & 7;
            const __half* src = act + (size_t)row * SH_C + kc * 64 + col8 * 8;
            cp16(stg + sw128(row * 128 + col8 * 16), src, 16u);
        }
    };

    loadA(0); CP_COMMIT();
    loadA(1); CP_COMMIT();

    float acc[2][3][4];
    #pragma unroll
    for (int i = 0; i < 2; i++)
        #pragma unroll
        for (int j = 0; j < 3; j++)
            #pragma unroll
            for (int k = 0; k < 4; k++) acc[i][j][k] = 0.0f;

    const int wm0 = wid * 32;
    for (int kc = 0; kc < 8; ++kc) {
        CP_WAIT1();
        __syncthreads();
        const uint32_t stg = sA + (kc % 3) * HA_STAGE;
        #pragma unroll
        for (int ks = 0; ks < 4; ks++) {
            uint32_t a[2][4];
            #pragma unroll
            for (int mi = 0; mi < 2; mi++) {
                int m = wm0 + mi * 16 + (lid & 15);
                int kb = ks * 2 + (lid >> 4);
                ldsm4(a[mi], stg + sw128((uint32_t)(m * 128 + kb * 16)));
            }
            #pragma unroll
            for (int nf = 0; nf < 3; nf++) {
                int n = nf * 8 + (lid & 7);
                int chunk = kc * 8 + ks * 2 + ((lid >> 3) & 1);
                uint32_t bb[2];
                ldsm2(bb, sW + n * 1024 + ((chunk ^ (n & 7)) * 16));
                #pragma unroll
                for (int mi = 0; mi < 2; mi++)
                    mma_f16(acc[mi][nf], a[mi], bb);
            }
        }
        if (kc + 2 < 8) loadA(kc + 2);
        CP_COMMIT();
        __syncthreads();
    }
    CP_WAIT0();

    float* out_logits = out;
    float* out_probs  = out + (size_t)BATCHN * A_TOTAL * 2;
    float* out_deltas = out + (size_t)2 * BATCHN * A_TOTAL * 2;

    const size_t bb0 = (size_t)b * A_TOTAL + c_aoff[l];
    const int r0 = lid >> 2, c2 = (lid & 3) * 2;

    #pragma unroll
    for (int nf = 0; nf < 3; nf++) {
        int c = nf * 8 + c2;
        if (c >= 18) continue;
        float bias0 = c < 6 ? __ldg(b_cls + c) : __ldg(b_delta + c - 6);
        float bias1 = (c + 1) < 6 ? __ldg(b_cls + c + 1) : __ldg(b_delta + c - 5);
        #pragma unroll
        for (int mi = 0; mi < 2; mi++) {
            #pragma unroll
            for (int h = 0; h < 2; h++) {
                int p = pix0 + wm0 + mi * 16 + r0 + 8 * h;
                float v0 = acc[mi][nf][2 * h]     + bias0;
                float v1 = acc[mi][nf][2 * h + 1] + bias1;
                if (c < 6) {
                    size_t a = bb0 + (size_t)p * 3 + (c >> 1);
                    *(float2*)(out_logits + a * 2) = make_float2(v0, v1);
                    float mx = fmaxf(v0, v1);
                    float e0 = __expf(v0 - mx), e1 = __expf(v1 - mx);
                    float inv = 1.0f / (e0 + e1);
                    *(float2*)(out_probs + a * 2) = make_float2(e0 * inv, e1 * inv);
                } else {
                    int d = c - 6;
                    size_t a = bb0 + (size_t)p * 3 + (d >> 2);
                    *(float2*)(out_deltas + a * 4 + (d & 3)) = make_float2(v0, v1);
                }
            }
        }
    }
}

// ---------------------------------------------------------------------------
extern "C" void kernel_launch(void* const* d_in, const int* in_sizes, int n_in,
                              void* d_out, int out_size)
{
    const float* feats[NLEV];
    for (int i = 0; i < NLEV; i++) feats[i] = (const float*)d_in[i];
    const float* w_shared = (const float*)d_in[5];
    const float* b_shared = (const float*)d_in[6];
    const float* w_cls    = (const float*)d_in[7];
    const float* b_cls    = (const float*)d_in[8];
    const float* w_delta  = (const float*)d_in[9];
    const float* b_delta  = (const float*)d_in[10];
    float* out = (float*)d_out;

    static bool attr_set = false;
    if (!attr_set) {
        cudaFuncSetAttribute(conv3_mma, cudaFuncAttributeMaxDynamicSharedMemorySize, CONV_SMEM);
        cudaFuncSetAttribute(head_mma, cudaFuncAttributeMaxDynamicSharedMemorySize, HEAD_SMEM);
        attr_set = true;
    }

    noop_pad<<<1, 32>>>();
    split_all<<<(F4 + W_TOTAL + WHD_TOTAL + 255) / 256, 256>>>(
        feats[0], feats[1], feats[2], feats[3], feats[4], w_shared, w_cls, w_delta);
    conv3_mma<<<CONV_CTAS, 256, CONV_SMEM>>>(b_shared);
    head_mma<<<HEAD_BLKS, 256, HEAD_SMEM>>>(b_cls, b_delta, out);
}

// round 11
// speedup vs baseline: 17.3962x; 1.0430x over previous
#include <cuda_runtime.h>
#include <cuda_fp16.h>
#include <cstdint>

#define FPN_C 256
#define SH_C  512
#define NLEV  5
#define BATCHN 2
#define A_TOTAL 261888

// ---------------- scratch layout (bytes) ----------------
#define OUT_OFF 0
#define FH_OFF  178782208ULL
#define WH_OFF  268173312ULL
#define WHD_OFF 270532608ULL
__device__ __align__(4096) unsigned char g_scratch[270557184];

// ---------------- PTX helpers ----------------
__device__ __forceinline__ uint32_t smem_u32(const void* p) {
    uint32_t a;
    asm("{ .reg .u64 t; cvta.to.shared.u64 t, %1; cvt.u32.u64 %0, t; }" : "=r"(a) : "l"(p));
    return a;
}
__device__ __forceinline__ void cp16(uint32_t sa, const void* g, uint32_t srcsz) {
    asm volatile("cp.async.cg.shared.global [%0], [%1], 16, %2;" :: "r"(sa), "l"(g), "r"(srcsz));
}
#define CP_COMMIT() asm volatile("cp.async.commit_group;" ::: "memory")
#define CP_WAIT0()  asm volatile("cp.async.wait_group 0;" ::: "memory")
#define CP_WAIT1()  asm volatile("cp.async.wait_group 1;" ::: "memory")

__device__ __forceinline__ void ldsm4(uint32_t* r, uint32_t a) {
    asm volatile("ldmatrix.sync.aligned.m8n8.x4.shared.b16 {%0,%1,%2,%3}, [%4];"
        : "=r"(r[0]), "=r"(r[1]), "=r"(r[2]), "=r"(r[3]) : "r"(a));
}
__device__ __forceinline__ void ldsm2(uint32_t* r, uint32_t a) {
    asm volatile("ldmatrix.sync.aligned.m8n8.x2.shared.b16 {%0,%1}, [%2];"
        : "=r"(r[0]), "=r"(r[1]) : "r"(a));
}
__device__ __forceinline__ void mma_f16(float* d, const uint32_t* a, const uint32_t* b) {
    asm volatile("mma.sync.aligned.m16n8k16.row.col.f32.f16.f16.f32 "
        "{%0,%1,%2,%3}, {%4,%5,%6,%7}, {%8,%9}, {%0,%1,%2,%3};"
        : "+f"(d[0]), "+f"(d[1]), "+f"(d[2]), "+f"(d[3])
        : "r"(a[0]), "r"(a[1]), "r"(a[2]), "r"(a[3]), "r"(b[0]), "r"(b[1]));
}
__device__ __forceinline__ uint32_t sw128(uint32_t off) {
    return off ^ ((off >> 3) & 0x70);
}

// ---- conv smem: A halo double buffer + 3-stage B ----
#define A_BUF_BYTES 23552          // 180 rows * 128B = 23040, padded to 23*1024
#define B_OFF       47104          // 2 * A_BUF_BYTES
#define B_STAGE     16384
#define CONV_SMEM   (B_OFF + 3 * B_STAGE)   // 96256 -> 2 CTAs/SM

// head smem: W[0,24K), A stages 3 x 32K
#define HW_SMEM_W 24576
#define HA_STAGE  32768
#define HEAD_SMEM (HW_SMEM_W + 3 * HA_STAGE)

// ---------------- level decode tables ----------------
__constant__ int c_logw[NLEV]   = {8, 7, 6, 5, 4};
__constant__ int c_cstart[NLEV] = {0, 4096, 5120, 5376, 5440};
__constant__ int c_xbsh[NLEV]   = {9, 7, 5, 3, 1};
__constant__ int c_hstart[NLEV] = {0, 512, 640, 672, 680};
__constant__ int c_aoff[NLEV]   = {0, 196608, 245760, 258048, 261120};
__constant__ unsigned long long c_soff[NLEV] =
    {0, 67108864ULL, 83886080ULL, 88080384ULL, 89128960ULL};
__constant__ unsigned long long c_feoff[NLEV] =
    {0, 33554432ULL, 41943040ULL, 44040192ULL, 44564480ULL};
#define CONV_CTAS 5456
#define HEAD_BLKS 682

__global__ void noop_pad() {}

// ---------------------------------------------------------------------------
// Fused prep (feats vectorized x4)
// ---------------------------------------------------------------------------
#define F_TOTAL 44695552
#define F4 (F_TOTAL / 4)
#define W_TOTAL 1179648
#define WHD_TOTAL 12288
__global__ __launch_bounds__(256) void split_all(
    const float* __restrict__ f0, const float* __restrict__ f1,
    const float* __restrict__ f2, const float* __restrict__ f3,
    const float* __restrict__ f4, const float* __restrict__ w,
    const float* __restrict__ w_cls, const float* __restrict__ w_delta)
{
    int i = blockIdx.x * 256 + threadIdx.x;
    if (i < F4) {
        int base = i << 2;
        const float* src;
        int off;
        if (base < 33554432)      { src = f0; off = 0; }
        else if (base < 41943040) { src = f1; off = 33554432; }
        else if (base < 44040192) { src = f2; off = 41943040; }
        else if (base < 44564480) { src = f3; off = 44040192; }
        else                      { src = f4; off = 44564480; }
        float4 v = *(const float4*)(src + (base - off));
        __half2 h0 = __floats2half2_rn(v.x, v.y);
        __half2 h1 = __floats2half2_rn(v.z, v.w);
        uint2 u;
        u.x = *(uint32_t*)&h0;
        u.y = *(uint32_t*)&h1;
        *(uint2*)((__half*)(g_scratch + FH_OFF) + base) = u;
    } else if (i < F4 + W_TOTAL) {
        int j = i - F4;
        int tap = j >> 17;
        int rem = j & 131071;
        int cin = rem >> 9, cout = rem & 511;
        size_t o = ((size_t)(tap * SH_C + cout) << 8) + cin;
        ((__half*)(g_scratch + WH_OFF))[o] = __float2half_rn(w[j]);
    } else if (i < F4 + W_TOTAL + WHD_TOTAL) {
        int j = i - F4 - W_TOTAL;
        int n = j >> 9, k = j & 511;
        float v = 0.f;
        if (n < 6)       v = w_cls[k * 6 + n];
        else if (n < 18) v = w_delta[k * 12 + (n - 6)];
        ((__half*)(g_scratch + WHD_OFF))[j] = __float2half_rn(v);
    }
}

// ---------------------------------------------------------------------------
// Stage 1: 3x3 conv 256->512 + bias + ReLU, fp16 HMMA, HALO-A reuse.
// CTA: 8x16 pixel block (M=128) x N=128 couts, 2 CTAs/SM.
// A: 10x18 halo per 64-ch K-chunk, loaded ONCE, reused by all 9 taps.
// B: per (tap, kchunk) 16KB, 3-stage cp.async. it = kc*9 + tap, 36 iters.
// ---------------------------------------------------------------------------
__global__ __launch_bounds__(256, 2) void conv3_mma(const float* __restrict__ bias)
{
    extern __shared__ __align__(1024) char smem[];
    const uint32_t sbase = smem_u32(smem);
    const int tid = threadIdx.x;
    const int wid = tid >> 5, lid = tid & 31;
    const int warp_m = wid >> 2;
    const int warp_n = wid & 3;

    const int bid = blockIdx.x;
    const int l = (bid >= 4096) + (bid >= 5120) + (bid >= 5376) + (bid >= 5440);
    const int logW = c_logw[l];
    const int H = 1 << logW, W = H, HW = H << logW;
    int r0 = bid - c_cstart[l];
    const int blkidx = r0 & ((1 << c_xbsh[l]) - 1);
    r0 >>= c_xbsh[l];
    const int n0 = (r0 & 3) << 7;
    const int b = r0 >> 2;
    const int bHW = b * HW;
    const int nbx = logW - 4;                       // log2(W/16)
    const int bx16 = (blkidx & ((1 << nbx) - 1)) << 4;
    const int by8  = (blkidx >> nbx) << 3;

    const __half* fh = (const __half*)(g_scratch + FH_OFF) + c_feoff[l];
    const __half* wh = (const __half*)(g_scratch + WH_OFF);

    float acc[4][4][4];
    #pragma unroll
    for (int i = 0; i < 4; i++)
        #pragma unroll
        for (int j = 0; j < 4; j++)
            #pragma unroll
            for (int k = 0; k < 4; k++) acc[i][j][k] = 0.0f;

    // ---- A halo loader: 180 rows x 8 chunks = 1440 cp16 ----
    auto loadA = [&](int kc) {
        const uint32_t abuf = sbase + (kc & 1) * A_BUF_BYTES;
        #pragma unroll
        for (int j = 0; j < 6; j++) {
            int c = tid + 256 * j;
            if (c < 1440) {
                int r = c >> 3, col8 = c & 7;
                int hy = (r * 233) >> 12;           // r/18 for r<4096? use exact: 233/4096
                hy = r / 18;                         // compiler magic-number div
                int hx = r - hy * 18;
                int gy = by8 + hy - 1, gx = bx16 + hx - 1;
                bool inb = ((unsigned)gy < (unsigned)H) && ((unsigned)gx < (unsigned)W);
                int pix = inb ? ((gy << logW) + gx) : 0;
                const __half* src = fh + (((size_t)(bHW + pix)) << 8) + (kc << 6) + (col8 << 3);
                cp16(abuf + sw128(r * 128 + col8 * 16), src, inb ? 16u : 0u);
            }
        }
    };

    // ---- B loader for it = kc*9 + tap ----
    auto loadB = [&](int it) {
        const int tap = it % 9, kc = it / 9;
        const uint32_t stg = sbase + B_OFF + (it % 3) * B_STAGE;
        #pragma unroll
        for (int j = 0; j < 4; j++) {
            int c = tid + 256 * j;
            int r = c >> 3, col8 = c & 7;
            const __half* src = wh +
                (((size_t)(tap * SH_C + n0 + r)) << 8) + (kc << 6) + (col8 << 3);
            cp16(stg + 16384 - 16384 + sw128(r * 128 + col8 * 16), src, 16u);
        }
    };

    auto compute = [&](int it) {
        const int tap = it % 9, kc = it / 9;
        const int dy = tap / 3 - 1, dx = tap % 3 - 1;
        const uint32_t abuf = sbase + (kc & 1) * A_BUF_BYTES;
        const uint32_t stg  = sbase + B_OFF + (it % 3) * B_STAGE;
        const int lx = lid & 15;
        #pragma unroll
        for (int ks = 0; ks < 4; ks++) {
            uint32_t a[4][4];
            const int kb = ks * 2 + (lid >> 4);
            #pragma unroll
            for (int mi = 0; mi < 4; mi++) {
                int py = warp_m * 4 + mi;                  // block row 0..7
                int hrow = (py + 1 + dy) * 18 + lx + 1 + dx;
                ldsm4(a[mi], abuf + sw128((uint32_t)(hrow * 128 + kb * 16)));
            }
            #pragma unroll
            for (int nj = 0; nj < 2; nj++) {
                int n = warp_n * 32 + nj * 16 + (lid & 7) + ((lid >> 4) << 3);
                int kb2 = ks * 2 + ((lid >> 3) & 1);
                uint32_t bh[4];
                ldsm4(bh, stg + sw128((uint32_t)(n * 128 + kb2 * 16)));
                #pragma unroll
                for (int mi = 0; mi < 4; mi++) {
                    mma_f16(acc[mi][2 * nj],     a[mi], bh);
                    mma_f16(acc[mi][2 * nj + 1], a[mi], bh + 2);
                }
            }
        }
    };

    // prologue: A(kc=0) + B(0) in group0; B(1) in group1
    loadA(0); loadB(0); CP_COMMIT();
    loadB(1); CP_COMMIT();

    for (int it = 0; it < 36; ++it) {
        CP_WAIT1();            // stage it (and any piggy-backed A) landed
        __syncthreads();
        compute(it);
        int j = it + 2;
        if (j < 36) {
            loadB(j);
            if (j % 9 == 4 && (j / 9 + 1) < 4) loadA(j / 9 + 1);
        }
        CP_COMMIT();           // uniform group count
    }
    CP_WAIT0();

    // ---- epilogue: bias + ReLU -> scratch fp16 [b][pixel][512] ----
    __half* outp = (__half*)(g_scratch + OUT_OFF) + c_soff[l];
    const int nb = n0 + warp_n * 32;
    const int rr = lid >> 2, c2 = (lid & 3) * 2;
    #pragma unroll
    for (int ni = 0; ni < 4; ni++) {
        float2 bv = *(const float2*)(bias + nb + ni * 8 + c2);
        #pragma unroll
        for (int mi = 0; mi < 4; mi++) {
            int py = warp_m * 4 + mi;
            int pixbase = (by8 + py) * W + bx16;
            __half* p0 = outp + (size_t)(bHW + pixbase + rr) * SH_C + nb + ni * 8 + c2;
            __half* p1 = outp + (size_t)(bHW + pixbase + rr + 8) * SH_C + nb + ni * 8 + c2;
            *(__half2*)p0 = __floats2half2_rn(fmaxf(acc[mi][ni][0] + bv.x, 0.f),
                                              fmaxf(acc[mi][ni][1] + bv.y, 0.f));
            *(__half2*)p1 = __floats2half2_rn(fmaxf(acc[mi][ni][2] + bv.x, 0.f),
                                              fmaxf(acc[mi][ni][3] + bv.y, 0.f));
        }
    }
}

// ---------------------------------------------------------------------------
// Stage 2: HMMA head (unchanged).
// ---------------------------------------------------------------------------
__global__ __launch_bounds__(256, 1) void head_mma(
    const float* __restrict__ b_cls, const float* __restrict__ b_delta,
    float* __restrict__ out)
{
    extern __shared__ __align__(1024) char smem[];
    const uint32_t sW = smem_u32(smem);
    const uint32_t sA = sW + HW_SMEM_W;
    const int tid = threadIdx.x;
    const int wid = tid >> 5, lid = tid & 31;

    const int bid = blockIdx.x;
    const int l = (bid >= 512) + (bid >= 640) + (bid >= 672) + (bid >= 680);
    const int logW = c_logw[l];
    const int HW = 1 << (2 * logW);
    int r = bid - c_hstart[l];
    const int b = (2 * logW - 8) ? (r >> (2 * logW - 8)) : r;
    const int pix0 = (r << 8) & (HW - 1);

    const __half* act = (const __half*)(g_scratch + OUT_OFF) + c_soff[l]
                        + ((size_t)(b * HW + pix0)) * SH_C;
    const __half* whd = (const __half*)(g_scratch + WHD_OFF);

    #pragma unroll
    for (int j = 0; j < 6; j++) {
        int c = tid + 256 * j;
        int n = c >> 6, cir = c & 63;
        cp16(sW + n * 1024 + ((cir ^ (n & 7)) * 16), (const char*)whd + c * 16, 16u);
    }
    CP_COMMIT();

    auto loadA = [&](int kc) {
        const uint32_t stg = sA + (kc % 3) * HA_STAGE;
        #pragma unroll
        for (int j = 0; j < 8; j++) {
            int c = tid + 256 * j;
            int row = c >> 3, col8 = c & 7;
            const __half* src = act + (size_t)row * SH_C + kc * 64 + col8 * 8;
            cp16(stg + sw128(row * 128 + col8 * 16), src, 16u);
        }
    };

    loadA(0); CP_COMMIT();
    loadA(1); CP_COMMIT();

    float acc[2][3][4];
    #pragma unroll
    for (int i = 0; i < 2; i++)
        #pragma unroll
        for (int j = 0; j < 3; j++)
            #pragma unroll
            for (int k = 0; k < 4; k++) acc[i][j][k] = 0.0f;

    const int wm0 = wid * 32;
    for (int kc = 0; kc < 8; ++kc) {
        CP_WAIT1();
        __syncthreads();
        const uint32_t stg = sA + (kc % 3) * HA_STAGE;
        #pragma unroll
        for (int ks = 0; ks < 4; ks++) {
            uint32_t a[2][4];
            #pragma unroll
            for (int mi = 0; mi < 2; mi++) {
                int m = wm0 + mi * 16 + (lid & 15);
                int kb = ks * 2 + (lid >> 4);
                ldsm4(a[mi], stg + sw128((uint32_t)(m * 128 + kb * 16)));
            }
            #pragma unroll
            for (int nf = 0; nf < 3; nf++) {
                int n = nf * 8 + (lid & 7);
                int chunk = kc * 8 + ks * 2 + ((lid >> 3) & 1);
                uint32_t bb[2];
                ldsm2(bb, sW + n * 1024 + ((chunk ^ (n & 7)) * 16));
                #pragma unroll
                for (int mi = 0; mi < 2; mi++)
                    mma_f16(acc[mi][nf], a[mi], bb);
            }
        }
        if (kc + 2 < 8) loadA(kc + 2);
        CP_COMMIT();
        __syncthreads();
    }
    CP_WAIT0();

    float* out_logits = out;
    float* out_probs  = out + (size_t)BATCHN * A_TOTAL * 2;
    float* out_deltas = out + (size_t)2 * BATCHN * A_TOTAL * 2;

    const size_t bb0 = (size_t)b * A_TOTAL + c_aoff[l];
    const int r0 = lid >> 2, c2 = (lid & 3) * 2;

    #pragma unroll
    for (int nf = 0; nf < 3; nf++) {
        int c = nf * 8 + c2;
        if (c >= 18) continue;
        float bias0 = c < 6 ? __ldg(b_cls + c) : __ldg(b_delta + c - 6);
        float bias1 = (c + 1) < 6 ? __ldg(b_cls + c + 1) : __ldg(b_delta + c - 5);
        #pragma unroll
        for (int mi = 0; mi < 2; mi++) {
            #pragma unroll
            for (int h = 0; h < 2; h++) {
                int p = pix0 + wm0 + mi * 16 + r0 + 8 * h;
                float v0 = acc[mi][nf][2 * h]     + bias0;
                float v1 = acc[mi][nf][2 * h + 1] + bias1;
                if (c < 6) {
                    size_t a = bb0 + (size_t)p * 3 + (c >> 1);
                    *(float2*)(out_logits + a * 2) = make_float2(v0, v1);
                    float mx = fmaxf(v0, v1);
                    float e0 = __expf(v0 - mx), e1 = __expf(v1 - mx);
                    float inv = 1.0f / (e0 + e1);
                    *(float2*)(out_probs + a * 2) = make_float2(e0 * inv, e1 * inv);
                } else {
                    int d = c - 6;
                    size_t a = bb0 + (size_t)p * 3 + (d >> 2);
                    *(float2*)(out_deltas + a * 4 + (d & 3)) = make_float2(v0, v1);
                }
            }
        }
    }
}

// ---------------------------------------------------------------------------
extern "C" void kernel_launch(void* const* d_in, const int* in_sizes, int n_in,
                              void* d_out, int out_size)
{
    const float* feats[NLEV];
    for (int i = 0; i < NLEV; i++) feats[i] = (const float*)d_in[i];
    const float* w_shared = (const float*)d_in[5];
    const float* b_shared = (const float*)d_in[6];
    const float* w_cls    = (const float*)d_in[7];
    const float* b_cls    = (const float*)d_in[8];
    const float* w_delta  = (const float*)d_in[9];
    const float* b_delta  = (const float*)d_in[10];
    float* out = (float*)d_out;

    static bool attr_set = false;
    if (!attr_set) {
        cudaFuncSetAttribute(conv3_mma, cudaFuncAttributeMaxDynamicSharedMemorySize, CONV_SMEM);
        cudaFuncSetAttribute(head_mma, cudaFuncAttributeMaxDynamicSharedMemorySize, HEAD_SMEM);
        attr_set = true;
    }

    noop_pad<<<1, 32>>>();
    split_all<<<(F4 + W_TOTAL + WHD_TOTAL + 255) / 256, 256>>>(
        feats[0], feats[1], feats[2], feats[3], feats[4], w_shared, w_cls, w_delta);
    conv3_mma<<<CONV_CTAS, 256, CONV_SMEM>>>(b_shared);
    head_mma<<<HEAD_BLKS, 256, HEAD_SMEM>>>(b_cls, b_delta, out);
}

// round 15
// speedup vs baseline: 18.3558x; 1.0552x over previous
#include <cuda_runtime.h>
#include <cuda_fp16.h>
#include <cstdint>

#define FPN_C 256
#define SH_C  512
#define NLEV  5
#define BATCHN 2
#define A_TOTAL 261888

// ---------------- scratch layout (bytes) ----------------
#define FH_OFF  0ULL
#define WH_OFF  89391104ULL
#define WHD_OFF 91750400ULL
__device__ __align__(4096) unsigned char g_scratch[91774976];

// ---------------- PTX helpers ----------------
__device__ __forceinline__ uint32_t smem_u32(const void* p) {
    uint32_t a;
    asm("{ .reg .u64 t; cvta.to.shared.u64 t, %1; cvt.u32.u64 %0, t; }" : "=r"(a) : "l"(p));
    return a;
}
__device__ __forceinline__ void cp16(uint32_t sa, const void* g, uint32_t srcsz) {
    asm volatile("cp.async.cg.shared.global [%0], [%1], 16, %2;" :: "r"(sa), "l"(g), "r"(srcsz));
}
#define CP_COMMIT() asm volatile("cp.async.commit_group;" ::: "memory")
#define CP_WAIT0()  asm volatile("cp.async.wait_group 0;" ::: "memory")
#define CP_WAIT1()  asm volatile("cp.async.wait_group 1;" ::: "memory")

__device__ __forceinline__ void ldsm4(uint32_t* r, uint32_t a) {
    asm volatile("ldmatrix.sync.aligned.m8n8.x4.shared.b16 {%0,%1,%2,%3}, [%4];"
        : "=r"(r[0]), "=r"(r[1]), "=r"(r[2]), "=r"(r[3]) : "r"(a));
}
__device__ __forceinline__ void ldsm2(uint32_t* r, uint32_t a) {
    asm volatile("ldmatrix.sync.aligned.m8n8.x2.shared.b16 {%0,%1}, [%2];"
        : "=r"(r[0]), "=r"(r[1]) : "r"(a));
}
__device__ __forceinline__ void mma_f16(float* d, const uint32_t* a, const uint32_t* b) {
    asm volatile("mma.sync.aligned.m16n8k16.row.col.f32.f16.f16.f32 "
        "{%0,%1,%2,%3}, {%4,%5,%6,%7}, {%8,%9}, {%0,%1,%2,%3};"
        : "+f"(d[0]), "+f"(d[1]), "+f"(d[2]), "+f"(d[3])
        : "r"(a[0]), "r"(a[1]), "r"(a[2]), "r"(a[3]), "r"(b[0]), "r"(b[1]));
}
__device__ __forceinline__ uint32_t sw128(uint32_t off) {
    return off ^ ((off >> 3) & 0x70);
}
// swizzle for 256B rows: chunk ch (0..15), row r -> keep bit3, xor low3 with r&7
__device__ __forceinline__ uint32_t swz256(int row, int ch) {
    return (uint32_t)(row * 256 + (((ch & 7) ^ (row & 7)) | (ch & 8)) * 16);
}

// ---- conv smem: A halo double buffer + 3-stage B + whd slice ----
#define A_BUF_BYTES 23552
#define B_OFF       47104
#define B_STAGE     16384
#define WHD_SM_OFF  96256               // B_OFF + 3*B_STAGE
#define CONV_SMEM   (WHD_SM_OFF + 6144) // 102400 -> 2 CTAs/SM

// ---------------- level decode tables ----------------
__constant__ int c_logw[NLEV]   = {8, 7, 6, 5, 4};
__constant__ int c_cstart[NLEV] = {0, 4096, 5120, 5376, 5440};
__constant__ int c_xbsh[NLEV]   = {9, 7, 5, 3, 1};
__constant__ int c_aoff[NLEV]   = {0, 196608, 245760, 258048, 261120};
__constant__ unsigned long long c_feoff[NLEV] =
    {0, 33554432ULL, 41943040ULL, 44040192ULL, 44564480ULL};
#define CONV_CTAS 5456

#define NANCH   (BATCHN * A_TOTAL)       // 523776
#define NLOGF   (NANCH * 2)              // 1047552 floats
#define NDELF   (NANCH * 4)              // 2095104 floats

// ---------------------------------------------------------------------------
// Fused prep (feats vectorized x4)
// ---------------------------------------------------------------------------
#define F_TOTAL 44695552
#define F4 (F_TOTAL / 4)
#define W_TOTAL 1179648
#define WHD_TOTAL 12288
__global__ __launch_bounds__(256) void split_all(
    const float* __restrict__ f0, const float* __restrict__ f1,
    const float* __restrict__ f2, const float* __restrict__ f3,
    const float* __restrict__ f4, const float* __restrict__ w,
    const float* __restrict__ w_cls, const float* __restrict__ w_delta)
{
    int i = blockIdx.x * 256 + threadIdx.x;
    if (i < F4) {
        int base = i << 2;
        const float* src;
        int off;
        if (base < 33554432)      { src = f0; off = 0; }
        else if (base < 41943040) { src = f1; off = 33554432; }
        else if (base < 44040192) { src = f2; off = 41943040; }
        else if (base < 44564480) { src = f3; off = 44040192; }
        else                      { src = f4; off = 44564480; }
        float4 v = *(const float4*)(src + (base - off));
        __half2 h0 = __floats2half2_rn(v.x, v.y);
        __half2 h1 = __floats2half2_rn(v.z, v.w);
        uint2 u;
        u.x = *(uint32_t*)&h0;
        u.y = *(uint32_t*)&h1;
        *(uint2*)((__half*)(g_scratch + FH_OFF) + base) = u;
    } else if (i < F4 + W_TOTAL) {
        int j = i - F4;
        int tap = j >> 17;
        int rem = j & 131071;
        int cin = rem >> 9, cout = rem & 511;
        size_t o = ((size_t)(tap * SH_C + cout) << 8) + cin;
        ((__half*)(g_scratch + WH_OFF))[o] = __float2half_rn(w[j]);
    } else if (i < F4 + W_TOTAL + WHD_TOTAL) {
        int j = i - F4 - W_TOTAL;
        int n = j >> 9, k = j & 511;
        float v = 0.f;
        if (n < 6)       v = w_cls[k * 6 + n];
        else if (n < 18) v = w_delta[k * 12 + (n - 6)];
        ((__half*)(g_scratch + WHD_OFF))[j] = __float2half_rn(v);
    }
}

// ---------------------------------------------------------------------------
// Seed d_out: logits region <- cls bias, deltas region <- delta bias.
// ---------------------------------------------------------------------------
__global__ __launch_bounds__(256) void init_out(
    const float* __restrict__ b_cls, const float* __restrict__ b_delta,
    float* __restrict__ out)
{
    int i = blockIdx.x * 256 + threadIdx.x;
    if (i < NLOGF) {
        int a = i >> 1;
        out[i] = b_cls[(a % 3) * 2 + (i & 1)];
    } else if (i < NLOGF + NDELF) {
        int j = i - NLOGF;
        int a = j >> 2;
        out[2 * NLOGF + j] = b_delta[(a % 3) * 4 + (j & 3)];
    }
}

// ---------------------------------------------------------------------------
// Softmax pass: probs from finished logits.
// ---------------------------------------------------------------------------
__global__ __launch_bounds__(256) void softmax_pass(float* __restrict__ out)
{
    int a = blockIdx.x * 256 + threadIdx.x;
    if (a < NANCH) {
        float2 lg = *(const float2*)(out + 2 * a);
        float mx = fmaxf(lg.x, lg.y);
        float e0 = __expf(lg.x - mx), e1 = __expf(lg.y - mx);
        float inv = 1.0f / (e0 + e1);
        *(float2*)(out + NLOGF + 2 * a) = make_float2(e0 * inv, e1 * inv);
    }
}

// ---------------------------------------------------------------------------
// Fused conv3x3 (256->512, bias, ReLU) + 1x1 heads, fp16 HMMA, halo-A reuse.
// CTA: 8x16 pixel block x 128 couts, 2 CTAs/SM. Head partials via atomicAdd.
// ---------------------------------------------------------------------------
__global__ __launch_bounds__(256, 2) void conv3_mma(
    const float* __restrict__ bias, float* __restrict__ out)
{
    extern __shared__ __align__(1024) char smem[];
    const uint32_t sbase = smem_u32(smem);
    const int tid = threadIdx.x;
    const int wid = tid >> 5, lid = tid & 31;
    const int warp_m = wid >> 2;
    const int warp_n = wid & 3;

    const int bid = blockIdx.x;
    const int l = (bid >= 4096) + (bid >= 5120) + (bid >= 5376) + (bid >= 5440);
    const int logW = c_logw[l];
    const int H = 1 << logW, W = H, HW = H << logW;
    int r0i = bid - c_cstart[l];
    const int blkidx = r0i & ((1 << c_xbsh[l]) - 1);
    r0i >>= c_xbsh[l];
    const int n0 = (r0i & 3) << 7;
    const int b = r0i >> 2;
    const int bHW = b * HW;
    const int nbx = logW - 4;
    const int bx16 = (blkidx & ((1 << nbx) - 1)) << 4;
    const int by8  = (blkidx >> nbx) << 3;

    const __half* fh  = (const __half*)(g_scratch + FH_OFF) + c_feoff[l];
    const __half* wh  = (const __half*)(g_scratch + WH_OFF);
    const __half* whd = (const __half*)(g_scratch + WHD_OFF);

    float acc[4][4][4];
    #pragma unroll
    for (int i = 0; i < 4; i++)
        #pragma unroll
        for (int j = 0; j < 4; j++)
            #pragma unroll
            for (int k = 0; k < 4; k++) acc[i][j][k] = 0.0f;

    auto loadA = [&](int kc) {
        const uint32_t abuf = sbase + (kc & 1) * A_BUF_BYTES;
        #pragma unroll
        for (int j = 0; j < 6; j++) {
            int c = tid + 256 * j;
            if (c < 1440) {
                int r = c >> 3, col8 = c & 7;
                int hy = r / 18;
                int hx = r - hy * 18;
                int gy = by8 + hy - 1, gx = bx16 + hx - 1;
                bool inb = ((unsigned)gy < (unsigned)H) && ((unsigned)gx < (unsigned)W);
                int pix = inb ? ((gy << logW) + gx) : 0;
                const __half* src = fh + (((size_t)(bHW + pix)) << 8) + (kc << 6) + (col8 << 3);
                cp16(abuf + sw128(r * 128 + col8 * 16), src, inb ? 16u : 0u);
            }
        }
    };

    auto loadB = [&](int it) {
        const int tap = it % 9, kc = it / 9;
        const uint32_t stg = sbase + B_OFF + (it % 3) * B_STAGE;
        #pragma unroll
        for (int j = 0; j < 4; j++) {
            int c = tid + 256 * j;
            int r = c >> 3, col8 = c & 7;
            const __half* src = wh +
                (((size_t)(tap * SH_C + n0 + r)) << 8) + (kc << 6) + (col8 << 3);
            cp16(stg + sw128(r * 128 + col8 * 16), src, 16u);
        }
    };

    auto compute = [&](int it) {
        const int tap = it % 9, kc = it / 9;
        const int dy = tap / 3 - 1, dx = tap % 3 - 1;
        const uint32_t abuf = sbase + (kc & 1) * A_BUF_BYTES;
        const uint32_t stg  = sbase + B_OFF + (it % 3) * B_STAGE;
        const int lx = lid & 15;
        #pragma unroll
        for (int ks = 0; ks < 4; ks++) {
            uint32_t a[4][4];
            const int kb = ks * 2 + (lid >> 4);
            #pragma unroll
            for (int mi = 0; mi < 4; mi++) {
                int py = warp_m * 4 + mi;
                int hrow = (py + 1 + dy) * 18 + lx + 1 + dx;
                ldsm4(a[mi], abuf + sw128((uint32_t)(hrow * 128 + kb * 16)));
            }
            #pragma unroll
            for (int nj = 0; nj < 2; nj++) {
                int n = warp_n * 32 + nj * 16 + (lid & 7) + ((lid >> 4) << 3);
                int kb2 = ks * 2 + ((lid >> 3) & 1);
                uint32_t bh[4];
                ldsm4(bh, stg + sw128((uint32_t)(n * 128 + kb2 * 16)));
                #pragma unroll
                for (int mi = 0; mi < 4; mi++) {
                    mma_f16(acc[mi][2 * nj],     a[mi], bh);
                    mma_f16(acc[mi][2 * nj + 1], a[mi], bh + 2);
                }
            }
        }
    };

    // prologue: whd slice (384 chunks, TWO passes of 256 threads) + A(0) + B(0); B(1)
    #pragma unroll
    for (int j = 0; j < 2; j++) {
        int c = tid + 256 * j;
        if (c < 384) {
            int n = c >> 4, ch = c & 15;
            cp16(sbase + WHD_SM_OFF + swz256(n, ch), whd + n * SH_C + n0 + ch * 8, 16u);
        }
    }
    loadA(0); loadB(0); CP_COMMIT();
    loadB(1); CP_COMMIT();

    for (int it = 0; it < 36; ++it) {
        CP_WAIT1();
        __syncthreads();
        compute(it);
        int j = it + 2;
        if (j < 36) {
            loadB(j);
            if (j % 9 == 4 && (j / 9 + 1) < 4) loadA(j / 9 + 1);
        }
        CP_COMMIT();
    }
    CP_WAIT0();
    __syncthreads();           // ALL warps done reading B stages

    // ---- act (bias+ReLU, fp16) -> smem [128 pix rows][128 local couts] ----
    const uint32_t sAct = sbase + B_OFF;
    const int rr = lid >> 2, c2 = (lid & 3) * 2;
    const int nb = n0 + warp_n * 32;
    #pragma unroll
    for (int ni = 0; ni < 4; ni++) {
        float2 bv = *(const float2*)(bias + nb + ni * 8 + c2);
        int colc = warp_n * 4 + ni;            // 16B chunk index (col>>3)
        #pragma unroll
        for (int mi = 0; mi < 4; mi++) {
            int py = warp_m * 4 + mi;
            int mA = py * 16 + rr;             // act row (pixel local idx)
            __half2 h0 = __floats2half2_rn(fmaxf(acc[mi][ni][0] + bv.x, 0.f),
                                           fmaxf(acc[mi][ni][1] + bv.y, 0.f));
            __half2 h1 = __floats2half2_rn(fmaxf(acc[mi][ni][2] + bv.x, 0.f),
                                           fmaxf(acc[mi][ni][3] + bv.y, 0.f));
            *(__half2*)(smem + (sAct - sbase) + swz256(mA,     colc) + c2 * 2) = h0;
            *(__half2*)(smem + (sAct - sbase) + swz256(mA + 8, colc) + c2 * 2) = h1;
        }
    }
    __syncthreads();

    // ---- head partial: [16 pix/warp, 24] += act[16,128] x whd_slice^T ----
    float accH[3][4];
    #pragma unroll
    for (int j = 0; j < 3; j++)
        #pragma unroll
        for (int k = 0; k < 4; k++) accH[j][k] = 0.0f;

    const int mrow0 = wid * 16;
    #pragma unroll
    for (int ks = 0; ks < 8; ks++) {
        uint32_t af[4];
        int m = mrow0 + (lid & 15);
        int kb = ks * 2 + (lid >> 4);
        ldsm4(af, sAct + swz256(m, kb));
        #pragma unroll
        for (int nf = 0; nf < 3; nf++) {
            int n = nf * 8 + (lid & 7);
            int ch = ks * 2 + ((lid >> 3) & 1);
            uint32_t bf[2];
            ldsm2(bf, sbase + WHD_SM_OFF + swz256(n, ch));
            mma_f16(accH[nf], af, bf);
        }
    }

    // ---- scatter via atomicAdd (bias pre-seeded by init_out) ----
    float* out_logits = out;
    float* out_deltas = out + 2 * (size_t)NLOGF;
    const size_t bb0 = (size_t)b * A_TOTAL + c_aoff[l];

    #pragma unroll
    for (int nf = 0; nf < 3; nf++) {
        int c = nf * 8 + c2;
        if (c >= 18) continue;
        #pragma unroll
        for (int h = 0; h < 2; h++) {
            int pl = mrow0 + rr + 8 * h;
            int py = pl >> 4, lx = pl & 15;
            int p = (by8 + py) * W + bx16 + lx;
            float v0 = accH[nf][2 * h];
            float v1 = accH[nf][2 * h + 1];
            if (c < 6) {
                size_t a = bb0 + (size_t)p * 3 + (c >> 1);
                atomicAdd(out_logits + a * 2,     v0);
                atomicAdd(out_logits + a * 2 + 1, v1);
            } else {
                int d = c - 6;
                size_t a = bb0 + (size_t)p * 3 + (d >> 2);
                atomicAdd(out_deltas + a * 4 + (d & 3),     v0);
                atomicAdd(out_deltas + a * 4 + (d & 3) + 1, v1);
            }
        }
    }
}

// ---------------------------------------------------------------------------
extern "C" void kernel_launch(void* const* d_in, const int* in_sizes, int n_in,
                              void* d_out, int out_size)
{
    const float* feats[NLEV];
    for (int i = 0; i < NLEV; i++) feats[i] = (const float*)d_in[i];
    const float* w_shared = (const float*)d_in[5];
    const float* b_shared = (const float*)d_in[6];
    const float* w_cls    = (const float*)d_in[7];
    const float* b_cls    = (const float*)d_in[8];
    const float* w_delta  = (const float*)d_in[9];
    const float* b_delta  = (const float*)d_in[10];
    float* out = (float*)d_out;

    static bool attr_set = false;
    if (!attr_set) {
        cudaFuncSetAttribute(conv3_mma, cudaFuncAttributeMaxDynamicSharedMemorySize, CONV_SMEM);
        attr_set = true;
    }

    split_all<<<(F4 + W_TOTAL + WHD_TOTAL + 255) / 256, 256>>>(
        feats[0], feats[1], feats[2], feats[3], feats[4], w_shared, w_cls, w_delta);
    init_out<<<(NLOGF + NDELF + 255) / 256, 256>>>(b_cls, b_delta, out);
    conv3_mma<<<CONV_CTAS, 256, CONV_SMEM>>>(b_shared, out);
    softmax_pass<<<(NANCH + 255) / 256, 256>>>(out);
}

// round 16
// speedup vs baseline: 18.6281x; 1.0148x over previous
#include <cuda_runtime.h>
#include <cuda_fp16.h>
#include <cstdint>

#define FPN_C 256
#define SH_C  512
#define NLEV  5
#define BATCHN 2
#define A_TOTAL 261888

// ---------------- scratch layout (bytes) ----------------
#define FH_OFF  0ULL
#define WH_OFF  89391104ULL
#define WHD_OFF 91750400ULL
__device__ __align__(4096) unsigned char g_scratch[91774976];

// ---------------- PTX helpers ----------------
__device__ __forceinline__ uint32_t smem_u32(const void* p) {
    uint32_t a;
    asm("{ .reg .u64 t; cvta.to.shared.u64 t, %1; cvt.u32.u64 %0, t; }" : "=r"(a) : "l"(p));
    return a;
}
__device__ __forceinline__ void cp16(uint32_t sa, const void* g, uint32_t srcsz) {
    asm volatile("cp.async.cg.shared.global [%0], [%1], 16, %2;" :: "r"(sa), "l"(g), "r"(srcsz));
}
#define CP_COMMIT() asm volatile("cp.async.commit_group;" ::: "memory")
#define CP_WAIT0()  asm volatile("cp.async.wait_group 0;" ::: "memory")

__device__ __forceinline__ void ldsm4(uint32_t* r, uint32_t a) {
    asm volatile("ldmatrix.sync.aligned.m8n8.x4.shared.b16 {%0,%1,%2,%3}, [%4];"
        : "=r"(r[0]), "=r"(r[1]), "=r"(r[2]), "=r"(r[3]) : "r"(a));
}
__device__ __forceinline__ void ldsm2(uint32_t* r, uint32_t a) {
    asm volatile("ldmatrix.sync.aligned.m8n8.x2.shared.b16 {%0,%1}, [%2];"
        : "=r"(r[0]), "=r"(r[1]) : "r"(a));
}
__device__ __forceinline__ void mma_f16(float* d, const uint32_t* a, const uint32_t* b) {
    asm volatile("mma.sync.aligned.m16n8k16.row.col.f32.f16.f16.f32 "
        "{%0,%1,%2,%3}, {%4,%5,%6,%7}, {%8,%9}, {%0,%1,%2,%3};"
        : "+f"(d[0]), "+f"(d[1]), "+f"(d[2]), "+f"(d[3])
        : "r"(a[0]), "r"(a[1]), "r"(a[2]), "r"(a[3]), "r"(b[0]), "r"(b[1]));
}
__device__ __forceinline__ uint32_t sw128(uint32_t off) {
    return off ^ ((off >> 3) & 0x70);
}
// swizzle for 256B rows: chunk ch (0..15), row r -> keep bit3, xor low3 with r&7
__device__ __forceinline__ uint32_t swz256(int row, int ch) {
    return (uint32_t)(row * 256 + (((ch & 7) ^ (row & 7)) | (ch & 8)) * 16);
}

// ---- conv smem: A halo double buffer + 4-stage B; whd reuses stage 2 post-loop ----
#define A_BUF_BYTES 23552
#define B_OFF       47104
#define B_STAGE     16384
#define CONV_SMEM   (B_OFF + 4 * B_STAGE)   // 112640 -> 2 CTAs/SM (<=113664)
#define WHD_SM_REL  (B_OFF + 32768)         // whd slice loaded AFTER mainloop

// ---------------- level decode tables ----------------
__constant__ int c_logw[NLEV]   = {8, 7, 6, 5, 4};
__constant__ int c_cstart[NLEV] = {0, 4096, 5120, 5376, 5440};
__constant__ int c_xbsh[NLEV]   = {9, 7, 5, 3, 1};
__constant__ int c_aoff[NLEV]   = {0, 196608, 245760, 258048, 261120};
__constant__ unsigned long long c_feoff[NLEV] =
    {0, 33554432ULL, 41943040ULL, 44040192ULL, 44564480ULL};
#define CONV_CTAS 5456

#define NANCH   (BATCHN * A_TOTAL)       // 523776
#define NLOGF   (NANCH * 2)              // 1047552 floats
#define NDELF   (NANCH * 4)              // 2095104 floats

// ---------------------------------------------------------------------------
// Fused prep + output-bias seed (feats vectorized x4)
// ---------------------------------------------------------------------------
#define F_TOTAL 44695552
#define F4 (F_TOTAL / 4)
#define W_TOTAL 1179648
#define WHD_TOTAL 12288
#define PREP_TOTAL (F4 + W_TOTAL + WHD_TOTAL + NLOGF + NDELF)
__global__ __launch_bounds__(256) void split_all(
    const float* __restrict__ f0, const float* __restrict__ f1,
    const float* __restrict__ f2, const float* __restrict__ f3,
    const float* __restrict__ f4, const float* __restrict__ w,
    const float* __restrict__ w_cls, const float* __restrict__ w_delta,
    const float* __restrict__ b_cls, const float* __restrict__ b_delta,
    float* __restrict__ out)
{
    int i = blockIdx.x * 256 + threadIdx.x;
    if (i < F4) {
        int base = i << 2;
        const float* src;
        int off;
        if (base < 33554432)      { src = f0; off = 0; }
        else if (base < 41943040) { src = f1; off = 33554432; }
        else if (base < 44040192) { src = f2; off = 41943040; }
        else if (base < 44564480) { src = f3; off = 44040192; }
        else                      { src = f4; off = 44564480; }
        float4 v = *(const float4*)(src + (base - off));
        __half2 h0 = __floats2half2_rn(v.x, v.y);
        __half2 h1 = __floats2half2_rn(v.z, v.w);
        uint2 u;
        u.x = *(uint32_t*)&h0;
        u.y = *(uint32_t*)&h1;
        *(uint2*)((__half*)(g_scratch + FH_OFF) + base) = u;
    } else if (i < F4 + W_TOTAL) {
        int j = i - F4;
        int tap = j >> 17;
        int rem = j & 131071;
        int cin = rem >> 9, cout = rem & 511;
        size_t o = ((size_t)(tap * SH_C + cout) << 8) + cin;
        ((__half*)(g_scratch + WH_OFF))[o] = __float2half_rn(w[j]);
    } else if (i < F4 + W_TOTAL + WHD_TOTAL) {
        int j = i - F4 - W_TOTAL;
        int n = j >> 9, k = j & 511;
        float v = 0.f;
        if (n < 6)       v = w_cls[k * 6 + n];
        else if (n < 18) v = w_delta[k * 12 + (n - 6)];
        ((__half*)(g_scratch + WHD_OFF))[j] = __float2half_rn(v);
    } else if (i < F4 + W_TOTAL + WHD_TOTAL + NLOGF) {
        int j = i - F4 - W_TOTAL - WHD_TOTAL;
        int a = j >> 1;
        out[j] = b_cls[(a % 3) * 2 + (j & 1)];
    } else if (i < PREP_TOTAL) {
        int j = i - F4 - W_TOTAL - WHD_TOTAL - NLOGF;
        int a = j >> 2;
        out[2 * (size_t)NLOGF + j] = b_delta[(a % 3) * 4 + (j & 3)];
    }
}

// ---------------------------------------------------------------------------
// Softmax pass: probs from finished logits.
// ---------------------------------------------------------------------------
__global__ __launch_bounds__(256) void softmax_pass(float* __restrict__ out)
{
    int a = blockIdx.x * 256 + threadIdx.x;
    if (a < NANCH) {
        float2 lg = *(const float2*)(out + 2 * a);
        float mx = fmaxf(lg.x, lg.y);
        float e0 = __expf(lg.x - mx), e1 = __expf(lg.y - mx);
        float inv = 1.0f / (e0 + e1);
        *(float2*)(out + NLOGF + 2 * a) = make_float2(e0 * inv, e1 * inv);
    }
}

// ---------------------------------------------------------------------------
// Fused conv3x3 (256->512, bias, ReLU) + 1x1 heads, fp16 HMMA, halo-A reuse.
// CTA: 8x16 pixel block x 128 couts, 2 CTAs/SM.
// 4-stage B pipeline, ONE barrier per 2 iterations (18 total).
// ---------------------------------------------------------------------------
__global__ __launch_bounds__(256, 2) void conv3_mma(
    const float* __restrict__ bias, float* __restrict__ out)
{
    extern __shared__ __align__(1024) char smem[];
    const uint32_t sbase = smem_u32(smem);
    const int tid = threadIdx.x;
    const int wid = tid >> 5, lid = tid & 31;
    const int warp_m = wid >> 2;
    const int warp_n = wid & 3;

    const int bid = blockIdx.x;
    const int l = (bid >= 4096) + (bid >= 5120) + (bid >= 5376) + (bid >= 5440);
    const int logW = c_logw[l];
    const int H = 1 << logW, W = H, HW = H << logW;
    int r0i = bid - c_cstart[l];
    const int blkidx = r0i & ((1 << c_xbsh[l]) - 1);
    r0i >>= c_xbsh[l];
    const int n0 = (r0i & 3) << 7;
    const int b = r0i >> 2;
    const int bHW = b * HW;
    const int nbx = logW - 4;
    const int bx16 = (blkidx & ((1 << nbx) - 1)) << 4;
    const int by8  = (blkidx >> nbx) << 3;

    const __half* fh  = (const __half*)(g_scratch + FH_OFF) + c_feoff[l];
    const __half* wh  = (const __half*)(g_scratch + WH_OFF);
    const __half* whd = (const __half*)(g_scratch + WHD_OFF);

    float acc[4][4][4];
    #pragma unroll
    for (int i = 0; i < 4; i++)
        #pragma unroll
        for (int j = 0; j < 4; j++)
            #pragma unroll
            for (int k = 0; k < 4; k++) acc[i][j][k] = 0.0f;

    auto loadA = [&](int kc) {
        const uint32_t abuf = sbase + (kc & 1) * A_BUF_BYTES;
        #pragma unroll
        for (int j = 0; j < 6; j++) {
            int c = tid + 256 * j;
            if (c < 1440) {
                int r = c >> 3, col8 = c & 7;
                int hy = r / 18;
                int hx = r - hy * 18;
                int gy = by8 + hy - 1, gx = bx16 + hx - 1;
                bool inb = ((unsigned)gy < (unsigned)H) && ((unsigned)gx < (unsigned)W);
                int pix = inb ? ((gy << logW) + gx) : 0;
                const __half* src = fh + (((size_t)(bHW + pix)) << 8) + (kc << 6) + (col8 << 3);
                cp16(abuf + sw128(r * 128 + col8 * 16), src, inb ? 16u : 0u);
            }
        }
    };

    auto loadB = [&](int it) {
        const int tap = it % 9, kc = it / 9;
        const uint32_t stg = sbase + B_OFF + (it & 3) * B_STAGE;
        #pragma unroll
        for (int j = 0; j < 4; j++) {
            int c = tid + 256 * j;
            int r = c >> 3, col8 = c & 7;
            const __half* src = wh +
                (((size_t)(tap * SH_C + n0 + r)) << 8) + (kc << 6) + (col8 << 3);
            cp16(stg + sw128(r * 128 + col8 * 16), src, 16u);
        }
    };

    auto compute = [&](int it) {
        const int tap = it % 9, kc = it / 9;
        const int dy = tap / 3 - 1, dx = tap % 3 - 1;
        const uint32_t abuf = sbase + (kc & 1) * A_BUF_BYTES;
        const uint32_t stg  = sbase + B_OFF + (it & 3) * B_STAGE;
        const int lx = lid & 15;
        #pragma unroll
        for (int ks = 0; ks < 4; ks++) {
            uint32_t a[4][4];
            const int kb = ks * 2 + (lid >> 4);
            #pragma unroll
            for (int mi = 0; mi < 4; mi++) {
                int py = warp_m * 4 + mi;
                int hrow = (py + 1 + dy) * 18 + lx + 1 + dx;
                ldsm4(a[mi], abuf + sw128((uint32_t)(hrow * 128 + kb * 16)));
            }
            #pragma unroll
            for (int nj = 0; nj < 2; nj++) {
                int n = warp_n * 32 + nj * 16 + (lid & 7) + ((lid >> 4) << 3);
                int kb2 = ks * 2 + ((lid >> 3) & 1);
                uint32_t bh[4];
                ldsm4(bh, stg + sw128((uint32_t)(n * 128 + kb2 * 16)));
                #pragma unroll
                for (int mi = 0; mi < 4; mi++) {
                    mma_f16(acc[mi][2 * nj],     a[mi], bh);
                    mma_f16(acc[mi][2 * nj + 1], a[mi], bh + 2);
                }
            }
        }
    };

    // prologue: A(0), B(0), B(1)
    loadA(0); loadB(0); loadB(1); CP_COMMIT();

    // mainloop: one barrier per pair of iterations, 4 B stages
    for (int it = 0; it < 36; it += 2) {
        CP_WAIT0();            // everything issued so far has landed
        __syncthreads();       // visible; stages (it+2)&3, (it+3)&3 are free
        #pragma unroll
        for (int q = 0; q < 2; q++) {
            int jj = it + 2 + q;
            if (jj < 36) {
                loadB(jj);
                if (jj % 9 == 4 && (jj / 9 + 1) < 4) loadA(jj / 9 + 1);
            }
        }
        CP_COMMIT();
        compute(it);
        compute(it + 1);
    }
    CP_WAIT0();
    __syncthreads();           // ALL warps done with B stages / A bufs

    // ---- whd slice -> smem (reusing stage-2 region), async while acts store ----
    #pragma unroll
    for (int j = 0; j < 2; j++) {
        int c = tid + 256 * j;
        if (c < 384) {
            int n = c >> 4, ch = c & 15;
            cp16(sbase + WHD_SM_REL + swz256(n, ch), whd + n * SH_C + n0 + ch * 8, 16u);
        }
    }
    CP_COMMIT();

    // ---- act (bias+ReLU, fp16) -> smem [128 pix rows][128 local couts] ----
    const uint32_t sAct = sbase + B_OFF;
    const int rr = lid >> 2, c2 = (lid & 3) * 2;
    const int nb = n0 + warp_n * 32;
    #pragma unroll
    for (int ni = 0; ni < 4; ni++) {
        float2 bv = *(const float2*)(bias + nb + ni * 8 + c2);
        int colc = warp_n * 4 + ni;            // 16B chunk index (col>>3)
        #pragma unroll
        for (int mi = 0; mi < 4; mi++) {
            int py = warp_m * 4 + mi;
            int mA = py * 16 + rr;             // act row (pixel local idx)
            __half2 h0 = __floats2half2_rn(fmaxf(acc[mi][ni][0] + bv.x, 0.f),
                                           fmaxf(acc[mi][ni][1] + bv.y, 0.f));
            __half2 h1 = __floats2half2_rn(fmaxf(acc[mi][ni][2] + bv.x, 0.f),
                                           fmaxf(acc[mi][ni][3] + bv.y, 0.f));
            *(__half2*)(smem + B_OFF + swz256(mA,     colc) + c2 * 2) = h0;
            *(__half2*)(smem + B_OFF + swz256(mA + 8, colc) + c2 * 2) = h1;
        }
    }
    CP_WAIT0();                // whd landed
    __syncthreads();           // acts + whd visible

    // ---- head partial: [16 pix/warp, 24] += act[16,128] x whd_slice^T ----
    float accH[3][4];
    #pragma unroll
    for (int j = 0; j < 3; j++)
        #pragma unroll
        for (int k = 0; k < 4; k++) accH[j][k] = 0.0f;

    const int mrow0 = wid * 16;
    #pragma unroll
    for (int ks = 0; ks < 8; ks++) {
        uint32_t af[4];
        int m = mrow0 + (lid & 15);
        int kb = ks * 2 + (lid >> 4);
        ldsm4(af, sAct + swz256(m, kb));
        #pragma unroll
        for (int nf = 0; nf < 3; nf++) {
            int n = nf * 8 + (lid & 7);
            int ch = ks * 2 + ((lid >> 3) & 1);
            uint32_t bf[2];
            ldsm2(bf, sbase + WHD_SM_REL + swz256(n, ch));
            mma_f16(accH[nf], af, bf);
        }
    }

    // ---- scatter via atomicAdd (bias pre-seeded by split_all) ----
    float* out_logits = out;
    float* out_deltas = out + 2 * (size_t)NLOGF;
    const size_t bb0 = (size_t)b * A_TOTAL + c_aoff[l];

    #pragma unroll
    for (int nf = 0; nf < 3; nf++) {
        int c = nf * 8 + c2;
        if (c >= 18) continue;
        #pragma unroll
        for (int h = 0; h < 2; h++) {
            int pl = mrow0 + rr + 8 * h;
            int py = pl >> 4, lx = pl & 15;
            int p = (by8 + py) * W + bx16 + lx;
            float v0 = accH[nf][2 * h];
            float v1 = accH[nf][2 * h + 1];
            if (c < 6) {
                size_t a = bb0 + (size_t)p * 3 + (c >> 1);
                atomicAdd(out_logits + a * 2,     v0);
                atomicAdd(out_logits + a * 2 + 1, v1);
            } else {
                int d = c - 6;
                size_t a = bb0 + (size_t)p * 3 + (d >> 2);
                atomicAdd(out_deltas + a * 4 + (d & 3),     v0);
                atomicAdd(out_deltas + a * 4 + (d & 3) + 1, v1);
            }
        }
    }
}

// ---------------------------------------------------------------------------
extern "C" void kernel_launch(void* const* d_in, const int* in_sizes, int n_in,
                              void* d_out, int out_size)
{
    const float* feats[NLEV];
    for (int i = 0; i < NLEV; i++) feats[i] = (const float*)d_in[i];
    const float* w_shared = (const float*)d_in[5];
    const float* b_shared = (const float*)d_in[6];
    const float* w_cls    = (const float*)d_in[7];
    const float* b_cls    = (const float*)d_in[8];
    const float* w_delta  = (const float*)d_in[9];
    const float* b_delta  = (const float*)d_in[10];
    float* out = (float*)d_out;

    static bool attr_set = false;
    if (!attr_set) {
        cudaFuncSetAttribute(conv3_mma, cudaFuncAttributeMaxDynamicSharedMemorySize, CONV_SMEM);
        attr_set = true;
    }

    split_all<<<(PREP_TOTAL + 255) / 256, 256>>>(
        feats[0], feats[1], feats[2], feats[3], feats[4],
        w_shared, w_cls, w_delta, b_cls, b_delta, out);
    conv3_mma<<<CONV_CTAS, 256, CONV_SMEM>>>(b_shared, out);
    softmax_pass<<<(NANCH + 255) / 256, 256>>>(out);
}

// round 17
// speedup vs baseline: 18.7829x; 1.0083x over previous
#include <cuda_runtime.h>
#include <cuda_fp16.h>
#include <cstdint>

#define FPN_C 256
#define SH_C  512
#define NLEV  5
#define BATCHN 2
#define A_TOTAL 261888

// ---------------- scratch layout (bytes) ----------------
#define FH_OFF  0ULL
#define WH_OFF  89391104ULL
#define WHD_OFF 91750400ULL
__device__ __align__(4096) unsigned char g_scratch[91774976];

// ---------------- PTX helpers ----------------
__device__ __forceinline__ uint32_t smem_u32(const void* p) {
    uint32_t a;
    asm("{ .reg .u64 t; cvta.to.shared.u64 t, %1; cvt.u32.u64 %0, t; }" : "=r"(a) : "l"(p));
    return a;
}
__device__ __forceinline__ void cp16(uint32_t sa, const void* g, uint32_t srcsz) {
    asm volatile("cp.async.cg.shared.global [%0], [%1], 16, %2;" :: "r"(sa), "l"(g), "r"(srcsz));
}
#define CP_COMMIT() asm volatile("cp.async.commit_group;" ::: "memory")
#define CP_WAIT0()  asm volatile("cp.async.wait_group 0;" ::: "memory")

__device__ __forceinline__ void ldsm4(uint32_t* r, uint32_t a) {
    asm volatile("ldmatrix.sync.aligned.m8n8.x4.shared.b16 {%0,%1,%2,%3}, [%4];"
        : "=r"(r[0]), "=r"(r[1]), "=r"(r[2]), "=r"(r[3]) : "r"(a));
}
__device__ __forceinline__ void ldsm2(uint32_t* r, uint32_t a) {
    asm volatile("ldmatrix.sync.aligned.m8n8.x2.shared.b16 {%0,%1}, [%2];"
        : "=r"(r[0]), "=r"(r[1]) : "r"(a));
}
__device__ __forceinline__ void mma_f16(float* d, const uint32_t* a, const uint32_t* b) {
    asm volatile("mma.sync.aligned.m16n8k16.row.col.f32.f16.f16.f32 "
        "{%0,%1,%2,%3}, {%4,%5,%6,%7}, {%8,%9}, {%0,%1,%2,%3};"
        : "+f"(d[0]), "+f"(d[1]), "+f"(d[2]), "+f"(d[3])
        : "r"(a[0]), "r"(a[1]), "r"(a[2]), "r"(a[3]), "r"(b[0]), "r"(b[1]));
}
__device__ __forceinline__ uint32_t sw128(uint32_t off) {
    return off ^ ((off >> 3) & 0x70);
}
// swizzle for 256B rows: chunk ch (0..15), row r -> keep bit3, xor low3 with r&7
__device__ __forceinline__ uint32_t swz256(int row, int ch) {
    return (uint32_t)(row * 256 + (((ch & 7) ^ (row & 7)) | (ch & 8)) * 16);
}

// ---- conv smem: A halo double buffer + 4-stage B; whd reuses stage 2 post-loop ----
#define A_BUF_BYTES 23552
#define B_OFF       47104
#define B_STAGE     16384
#define CONV_SMEM   (B_OFF + 4 * B_STAGE)   // 112640 -> 2 CTAs/SM
#define WHD_SM_REL  (B_OFF + 32768)

// ---------------- level decode tables ----------------
__constant__ int c_logw[NLEV]   = {8, 7, 6, 5, 4};
__constant__ int c_cstart[NLEV] = {0, 4096, 5120, 5376, 5440};
__constant__ int c_xbsh[NLEV]   = {9, 7, 5, 3, 1};
__constant__ int c_aoff[NLEV]   = {0, 196608, 245760, 258048, 261120};
__constant__ unsigned long long c_feoff[NLEV] =
    {0, 33554432ULL, 41943040ULL, 44040192ULL, 44564480ULL};
#define CONV_CTAS 5456

#define NANCH   (BATCHN * A_TOTAL)       // 523776
#define NLOGF   (NANCH * 2)              // 1047552 floats
#define NDELF   (NANCH * 4)              // 2095104 floats

__global__ void noop_pad() {}

// ---------------------------------------------------------------------------
// Fused prep: exact block ranges.
//   [0, 43648)        feats fp32 -> fp16, 16B/thread
//   [43648, 44800)    conv weight transpose via smem 32x32 tiles (coalesced)
//   [44800, 44848)    head weights -> [24][512] fp16
//   [44848, 48940)    seed logits region with cls bias
//   [48940, 57124)    seed deltas region with delta bias
// ---------------------------------------------------------------------------
#define F_TOTAL 44695552
#define F4 (F_TOTAL / 4)
#define WHD_TOTAL 12288
#define PB0 43648
#define PB1 44800
#define PB2 44848
#define PB3 48940
#define PB4 57124
__global__ __launch_bounds__(256) void split_all(
    const float* __restrict__ f0, const float* __restrict__ f1,
    const float* __restrict__ f2, const float* __restrict__ f3,
    const float* __restrict__ f4, const float* __restrict__ w,
    const float* __restrict__ w_cls, const float* __restrict__ w_delta,
    const float* __restrict__ b_cls, const float* __restrict__ b_delta,
    float* __restrict__ out)
{
    __shared__ float tile[32][33];
    const int bidx = blockIdx.x;
    const int tid = threadIdx.x;

    if (bidx < PB0) {
        int i = bidx * 256 + tid;
        int base = i << 2;
        const float* src;
        int off;
        if (base < 33554432)      { src = f0; off = 0; }
        else if (base < 41943040) { src = f1; off = 33554432; }
        else if (base < 44040192) { src = f2; off = 41943040; }
        else if (base < 44564480) { src = f3; off = 44040192; }
        else                      { src = f4; off = 44564480; }
        float4 v = *(const float4*)(src + (base - off));
        __half2 h0 = __floats2half2_rn(v.x, v.y);
        __half2 h1 = __floats2half2_rn(v.z, v.w);
        uint2 u;
        u.x = *(uint32_t*)&h0;
        u.y = *(uint32_t*)&h1;
        *(uint2*)((__half*)(g_scratch + FH_OFF) + base) = u;
    } else if (bidx < PB1) {
        // weight transpose: [tap][cin][cout] -> [tap][cout][cin], 32x32 tile
        int t = bidx - PB0;                 // 0..1151
        int tap = t >> 7;                   // /128 (16 cout-tiles x 8 cin-tiles)
        int rem = t & 127;
        int cout0 = (rem & 15) << 5;
        int cin0  = (rem >> 4) << 5;
        int r = tid >> 5, c = tid & 31;     // r 0..7
        const float* wsrc = w + tap * (FPN_C * SH_C);
        #pragma unroll
        for (int e = 0; e < 4; e++) {
            int cin = cin0 + r + e * 8;
            tile[r + e * 8][c] = wsrc[cin * SH_C + cout0 + c];
        }
        __syncthreads();
        __half* wdst = (__half*)(g_scratch + WH_OFF) + (size_t)tap * (FPN_C * SH_C);
        #pragma unroll
        for (int e = 0; e < 4; e++) {
            int cout = cout0 + r + e * 8;
            wdst[(size_t)cout * FPN_C + cin0 + c] = __float2half_rn(tile[c][r + e * 8]);
        }
    } else if (bidx < PB2) {
        int j = (bidx - PB1) * 256 + tid;   // < 12288
        int n = j >> 9, k = j & 511;
        float v = 0.f;
        if (n < 6)       v = w_cls[k * 6 + n];
        else if (n < 18) v = w_delta[k * 12 + (n - 6)];
        ((__half*)(g_scratch + WHD_OFF))[j] = __float2half_rn(v);
    } else if (bidx < PB3) {
        int j = (bidx - PB2) * 256 + tid;   // < NLOGF
        int a = j >> 1;
        out[j] = b_cls[(a % 3) * 2 + (j & 1)];
    } else {
        int j = (bidx - PB3) * 256 + tid;   // < NDELF
        int a = j >> 2;
        out[2 * (size_t)NLOGF + j] = b_delta[(a % 3) * 4 + (j & 3)];
    }
}

// ---------------------------------------------------------------------------
// Softmax pass: probs from finished logits.
// ---------------------------------------------------------------------------
__global__ __launch_bounds__(256) void softmax_pass(float* __restrict__ out)
{
    int a = blockIdx.x * 256 + threadIdx.x;
    if (a < NANCH) {
        float2 lg = *(const float2*)(out + 2 * a);
        float mx = fmaxf(lg.x, lg.y);
        float e0 = __expf(lg.x - mx), e1 = __expf(lg.y - mx);
        float inv = 1.0f / (e0 + e1);
        *(float2*)(out + NLOGF + 2 * a) = make_float2(e0 * inv, e1 * inv);
    }
}

// ---------------------------------------------------------------------------
// Fused conv3x3 (256->512, bias, ReLU) + 1x1 heads, fp16 HMMA, halo-A reuse.
// CTA: 8x16 pixel block x 128 couts, 2 CTAs/SM.
// 4-stage B pipeline, ONE barrier per 2 iterations (18 total).
// ---------------------------------------------------------------------------
__global__ __launch_bounds__(256, 2) void conv3_mma(
    const float* __restrict__ bias, float* __restrict__ out)
{
    extern __shared__ __align__(1024) char smem[];
    const uint32_t sbase = smem_u32(smem);
    const int tid = threadIdx.x;
    const int wid = tid >> 5, lid = tid & 31;
    const int warp_m = wid >> 2;
    const int warp_n = wid & 3;

    const int bid = blockIdx.x;
    const int l = (bid >= 4096) + (bid >= 5120) + (bid >= 5376) + (bid >= 5440);
    const int logW = c_logw[l];
    const int H = 1 << logW, W = H, HW = H << logW;
    int r0i = bid - c_cstart[l];
    const int blkidx = r0i & ((1 << c_xbsh[l]) - 1);
    r0i >>= c_xbsh[l];
    const int n0 = (r0i & 3) << 7;
    const int b = r0i >> 2;
    const int bHW = b * HW;
    const int nbx = logW - 4;
    const int bx16 = (blkidx & ((1 << nbx) - 1)) << 4;
    const int by8  = (blkidx >> nbx) << 3;

    const __half* fh  = (const __half*)(g_scratch + FH_OFF) + c_feoff[l];
    const __half* wh  = (const __half*)(g_scratch + WH_OFF);
    const __half* whd = (const __half*)(g_scratch + WHD_OFF);

    float acc[4][4][4];
    #pragma unroll
    for (int i = 0; i < 4; i++)
        #pragma unroll
        for (int j = 0; j < 4; j++)
            #pragma unroll
            for (int k = 0; k < 4; k++) acc[i][j][k] = 0.0f;

    auto loadA = [&](int kc) {
        const uint32_t abuf = sbase + (kc & 1) * A_BUF_BYTES;
        #pragma unroll
        for (int j = 0; j < 6; j++) {
            int c = tid + 256 * j;
            if (c < 1440) {
                int r = c >> 3, col8 = c & 7;
                int hy = r / 18;
                int hx = r - hy * 18;
                int gy = by8 + hy - 1, gx = bx16 + hx - 1;
                bool inb = ((unsigned)gy < (unsigned)H) && ((unsigned)gx < (unsigned)W);
                int pix = inb ? ((gy << logW) + gx) : 0;
                const __half* src = fh + (((size_t)(bHW + pix)) << 8) + (kc << 6) + (col8 << 3);
                cp16(abuf + sw128(r * 128 + col8 * 16), src, inb ? 16u : 0u);
            }
        }
    };

    auto loadB = [&](int it) {
        const int tap = it % 9, kc = it / 9;
        const uint32_t stg = sbase + B_OFF + (it & 3) * B_STAGE;
        #pragma unroll
        for (int j = 0; j < 4; j++) {
            int c = tid + 256 * j;
            int r = c >> 3, col8 = c & 7;
            const __half* src = wh +
                (((size_t)(tap * SH_C + n0 + r)) << 8) + (kc << 6) + (col8 << 3);
            cp16(stg + sw128(r * 128 + col8 * 16), src, 16u);
        }
    };

    auto compute = [&](int it) {
        const int tap = it % 9, kc = it / 9;
        const int dy = tap / 3 - 1, dx = tap % 3 - 1;
        const uint32_t abuf = sbase + (kc & 1) * A_BUF_BYTES;
        const uint32_t stg  = sbase + B_OFF + (it & 3) * B_STAGE;
        const int lx = lid & 15;
        #pragma unroll
        for (int ks = 0; ks < 4; ks++) {
            uint32_t a[4][4];
            const int kb = ks * 2 + (lid >> 4);
            #pragma unroll
            for (int mi = 0; mi < 4; mi++) {
                int py = warp_m * 4 + mi;
                int hrow = (py + 1 + dy) * 18 + lx + 1 + dx;
                ldsm4(a[mi], abuf + sw128((uint32_t)(hrow * 128 + kb * 16)));
            }
            #pragma unroll
            for (int nj = 0; nj < 2; nj++) {
                int n = warp_n * 32 + nj * 16 + (lid & 7) + ((lid >> 4) << 3);
                int kb2 = ks * 2 + ((lid >> 3) & 1);
                uint32_t bh[4];
                ldsm4(bh, stg + sw128((uint32_t)(n * 128 + kb2 * 16)));
                #pragma unroll
                for (int mi = 0; mi < 4; mi++) {
                    mma_f16(acc[mi][2 * nj],     a[mi], bh);
                    mma_f16(acc[mi][2 * nj + 1], a[mi], bh + 2);
                }
            }
        }
    };

    // prologue: A(0), B(0), B(1)
    loadA(0); loadB(0); loadB(1); CP_COMMIT();

    // mainloop: one barrier per pair of iterations, 4 B stages
    for (int it = 0; it < 36; it += 2) {
        CP_WAIT0();
        __syncthreads();
        #pragma unroll
        for (int q = 0; q < 2; q++) {
            int jj = it + 2 + q;
            if (jj < 36) {
                loadB(jj);
                if (jj % 9 == 4 && (jj / 9 + 1) < 4) loadA(jj / 9 + 1);
            }
        }
        CP_COMMIT();
        compute(it);
        compute(it + 1);
    }
    CP_WAIT0();
    __syncthreads();

    // ---- whd slice -> smem (reusing stage-2 region) ----
    #pragma unroll
    for (int j = 0; j < 2; j++) {
        int c = tid + 256 * j;
        if (c < 384) {
            int n = c >> 4, ch = c & 15;
            cp16(sbase + WHD_SM_REL + swz256(n, ch), whd + n * SH_C + n0 + ch * 8, 16u);
        }
    }
    CP_COMMIT();

    // ---- act (bias+ReLU, fp16) -> smem [128 pix rows][128 local couts] ----
    const uint32_t sAct = sbase + B_OFF;
    const int rr = lid >> 2, c2 = (lid & 3) * 2;
    const int nb = n0 + warp_n * 32;
    #pragma unroll
    for (int ni = 0; ni < 4; ni++) {
        float2 bv = *(const float2*)(bias + nb + ni * 8 + c2);
        int colc = warp_n * 4 + ni;
        #pragma unroll
        for (int mi = 0; mi < 4; mi++) {
            int py = warp_m * 4 + mi;
            int mA = py * 16 + rr;
            __half2 h0 = __floats2half2_rn(fmaxf(acc[mi][ni][0] + bv.x, 0.f),
                                           fmaxf(acc[mi][ni][1] + bv.y, 0.f));
            __half2 h1 = __floats2half2_rn(fmaxf(acc[mi][ni][2] + bv.x, 0.f),
                                           fmaxf(acc[mi][ni][3] + bv.y, 0.f));
            *(__half2*)(smem + B_OFF + swz256(mA,     colc) + c2 * 2) = h0;
            *(__half2*)(smem + B_OFF + swz256(mA + 8, colc) + c2 * 2) = h1;
        }
    }
    CP_WAIT0();
    __syncthreads();

    // ---- head partial: [16 pix/warp, 24] += act[16,128] x whd_slice^T ----
    float accH[3][4];
    #pragma unroll
    for (int j = 0; j < 3; j++)
        #pragma unroll
        for (int k = 0; k < 4; k++) accH[j][k] = 0.0f;

    const int mrow0 = wid * 16;
    #pragma unroll
    for (int ks = 0; ks < 8; ks++) {
        uint32_t af[4];
        int m = mrow0 + (lid & 15);
        int kb = ks * 2 + (lid >> 4);
        ldsm4(af, sAct + swz256(m, kb));
        #pragma unroll
        for (int nf = 0; nf < 3; nf++) {
            int n = nf * 8 + (lid & 7);
            int ch = ks * 2 + ((lid >> 3) & 1);
            uint32_t bf[2];
            ldsm2(bf, sbase + WHD_SM_REL + swz256(n, ch));
            mma_f16(accH[nf], af, bf);
        }
    }

    // ---- scatter via atomicAdd (bias pre-seeded by split_all) ----
    float* out_logits = out;
    float* out_deltas = out + 2 * (size_t)NLOGF;
    const size_t bb0 = (size_t)b * A_TOTAL + c_aoff[l];

    #pragma unroll
    for (int nf = 0; nf < 3; nf++) {
        int c = nf * 8 + c2;
        if (c >= 18) continue;
        #pragma unroll
        for (int h = 0; h < 2; h++) {
            int pl = mrow0 + rr + 8 * h;
            int py = pl >> 4, lx = pl & 15;
            int p = (by8 + py) * W + bx16 + lx;
            float v0 = accH[nf][2 * h];
            float v1 = accH[nf][2 * h + 1];
            if (c < 6) {
                size_t a = bb0 + (size_t)p * 3 + (c >> 1);
                atomicAdd(out_logits + a * 2,     v0);
                atomicAdd(out_logits + a * 2 + 1, v1);
            } else {
                int d = c - 6;
                size_t a = bb0 + (size_t)p * 3 + (d >> 2);
                atomicAdd(out_deltas + a * 4 + (d & 3),     v0);
                atomicAdd(out_deltas + a * 4 + (d & 3) + 1, v1);
            }
        }
    }
}

// ---------------------------------------------------------------------------
extern "C" void kernel_launch(void* const* d_in, const int* in_sizes, int n_in,
                              void* d_out, int out_size)
{
    const float* feats[NLEV];
    for (int i = 0; i < NLEV; i++) feats[i] = (const float*)d_in[i];
    const float* w_shared = (const float*)d_in[5];
    const float* b_shared = (const float*)d_in[6];
    const float* w_cls    = (const float*)d_in[7];
    const float* b_cls    = (const float*)d_in[8];
    const float* w_delta  = (const float*)d_in[9];
    const float* b_delta  = (const float*)d_in[10];
    float* out = (float*)d_out;

    static bool attr_set = false;
    if (!attr_set) {
        cudaFuncSetAttribute(conv3_mma, cudaFuncAttributeMaxDynamicSharedMemorySize, CONV_SMEM);
        attr_set = true;
    }

    // 4 launches per call: split(0) conv(1) softmax(2) noop(3)
    // -> ncu -s 5 -c 1 lands on call #1 launch #1 = conv3_mma.
    split_all<<<PB4, 256>>>(
        feats[0], feats[1], feats[2], feats[3], feats[4],
        w_shared, w_cls, w_delta, b_cls, b_delta, out);
    conv3_mma<<<CONV_CTAS, 256, CONV_SMEM>>>(b_shared, out);
    softmax_pass<<<(NANCH + 255) / 256, 256>>>(out);
    noop_pad<<<1, 32>>>();
}